// round 7
// baseline (speedup 1.0000x reference)
#include <cuda_runtime.h>
#include <cuda_bf16.h>
#include <cuda_fp16.h>
#include <math.h>
#include <stdint.h>

// Problem constants (B=8, S=2048, D=2048, H=2048, E=4, TOP_K=2)
#define NTOK 16384
#define DDIM 2048
#define HDIM 2048
#define NEXP 4
#define NCH  16              // K / 128 chunks (int8)

// Tile config: 128M x 128N CTA, 64x32 warp tiles (8 warps: 2M x 4N), BK=128 int8
#define BM 128
#define BN 128
#define TILE 16384                       // 128 rows x 128B
#define STAGE (4 * TILE)                 // A1 A2 B1 B2 = 64KB
#define NSTG 3
#define SMEM_TOTAL (1024 + NSTG * STAGE) // 197632

#define QS 32000.0f                      // int16 quant range

// ---------------------------------------------------------------------------
// Scratch (static device arrays — no runtime allocation)
// ---------------------------------------------------------------------------
__device__ int   g_cnt[NEXP];
__device__ int   g_tok[NEXP][NTOK];
__device__ float g_wgt[NEXP][NTOK];
__device__ int   g_rank[NEXP][NTOK];

__device__ __align__(16) int8_t g_x1[(size_t)NTOK * DDIM];     // hi limb
__device__ __align__(16) int8_t g_x2[(size_t)NTOK * DDIM];     // lo limb
__device__ float  g_sx[NTOK];

__device__ __align__(16) int8_t g_w1q1[(size_t)NEXP * HDIM * DDIM];  // [e][n][k]
__device__ __align__(16) int8_t g_w1q2[(size_t)NEXP * HDIM * DDIM];
__device__ float  g_sw1[NEXP * HDIM];
__device__ __align__(16) int8_t g_w2q1[(size_t)NEXP * HDIM * HDIM];
__device__ __align__(16) int8_t g_w2q2[(size_t)NEXP * HDIM * HDIM];
__device__ float  g_sw2[NEXP * HDIM];

__device__ __align__(16) __half g_h1f[(size_t)NEXP * NTOK * HDIM];   // gemm1 out staging
__device__ __align__(16) int8_t g_h1q1[(size_t)NEXP * NTOK * HDIM];
__device__ __align__(16) int8_t g_h1q2[(size_t)NEXP * NTOK * HDIM];
__device__ float  g_sh1[NEXP * NTOK];

__device__ __align__(16) float g_outr[2][(size_t)NTOK * HDIM];       // rank-split partials

// ---------------------------------------------------------------------------
// Helpers
// ---------------------------------------------------------------------------
__device__ __forceinline__ uint32_t smem_u32(const void* p) {
    uint32_t a;
    asm("{ .reg .u64 t; cvta.to.shared.u64 t, %1; cvt.u32.u64 %0, t; }"
        : "=r"(a) : "l"(p));
    return a;
}
__device__ __forceinline__ uint32_t swz(uint32_t row, uint32_t byteoff) {
    uint32_t c16 = byteoff >> 4, lo = byteoff & 15;
    return row * 128 + (((c16 ^ (row & 7)) & 7) << 4) + lo;
}
__device__ __forceinline__ void cp16(uint32_t saddr, const void* gaddr) {
    asm volatile("cp.async.cg.shared.global [%0], [%1], 16;" :: "r"(saddr), "l"(gaddr));
}
#define CP_COMMIT() asm volatile("cp.async.commit_group;" ::: "memory")
#define CP_WAIT0()  asm volatile("cp.async.wait_group 0;" ::: "memory")
#define CP_WAIT1()  asm volatile("cp.async.wait_group 1;" ::: "memory")

__device__ __forceinline__ void ldsm_x4(uint32_t* r, uint32_t addr) {
    asm volatile("ldmatrix.sync.aligned.m8n8.x4.shared.b16 {%0,%1,%2,%3}, [%4];"
        : "=r"(r[0]), "=r"(r[1]), "=r"(r[2]), "=r"(r[3]) : "r"(addr));
}
__device__ __forceinline__ void imma(int* d, const uint32_t* a, const uint32_t* b) {
    asm volatile(
        "mma.sync.aligned.m16n8k32.row.col.s32.s8.s8.s32 "
        "{%0,%1,%2,%3}, {%4,%5,%6,%7}, {%8,%9}, {%0,%1,%2,%3};"
        : "+r"(d[0]), "+r"(d[1]), "+r"(d[2]), "+r"(d[3])
        : "r"(a[0]), "r"(a[1]), "r"(a[2]), "r"(a[3]), "r"(b[0]), "r"(b[1]));
}
// split a float (pre-scaled) into hi/lo int8 limbs of its int16 quantization
__device__ __forceinline__ void q16split(float v, float inv, int8_t& hi, int8_t& lo) {
    int v16 = __float2int_rn(v * inv);
    int l = (v16 << 24) >> 24;
    int h = (v16 - l) >> 8;
    hi = (int8_t)h; lo = (int8_t)l;
}

// ---------------------------------------------------------------------------
__global__ void reset_kernel() {
    if (threadIdx.x < NEXP) g_cnt[threadIdx.x] = 0;
}

// x fp32 -> per-row scale + int8 hi/lo planes. One warp per token row.
__global__ void quant_x(const float* __restrict__ x) {
    int row = blockIdx.x * 8 + (threadIdx.x >> 5);
    int lane = threadIdx.x & 31;
    const float4* src = (const float4*)(x + (size_t)row * DDIM);
    float4 v[16];
    float m = 0.f;
#pragma unroll
    for (int j = 0; j < 16; j++) {
        v[j] = src[lane + j * 32];
        m = fmaxf(m, fmaxf(fmaxf(fabsf(v[j].x), fabsf(v[j].y)),
                           fmaxf(fabsf(v[j].z), fabsf(v[j].w))));
    }
#pragma unroll
    for (int o = 16; o; o >>= 1) m = fmaxf(m, __shfl_xor_sync(0xffffffffu, m, o));
    float s = m / QS;
    float inv = (m > 0.f) ? QS / m : 0.f;
    if (lane == 0) g_sx[row] = s;
    uint32_t* p1 = (uint32_t*)(g_x1 + (size_t)row * DDIM);
    uint32_t* p2 = (uint32_t*)(g_x2 + (size_t)row * DDIM);
#pragma unroll
    for (int j = 0; j < 16; j++) {
        int8_t h0, l0, h1, l1, h2, l2, h3, l3;
        q16split(v[j].x, inv, h0, l0); q16split(v[j].y, inv, h1, l1);
        q16split(v[j].z, inv, h2, l2); q16split(v[j].w, inv, h3, l3);
        uint32_t hw = (uint8_t)h0 | ((uint32_t)(uint8_t)h1 << 8) |
                      ((uint32_t)(uint8_t)h2 << 16) | ((uint32_t)(uint8_t)h3 << 24);
        uint32_t lw = (uint8_t)l0 | ((uint32_t)(uint8_t)l1 << 8) |
                      ((uint32_t)(uint8_t)l2 << 16) | ((uint32_t)(uint8_t)l3 << 24);
        p1[lane + j * 32] = hw;
        p2[lane + j * 32] = lw;
    }
}

// per-(e,n) column max of |w[e][k][n]| -> scale. which: 0 = w1, 1 = w2.
// NOTE: device globals selected INSIDE the kernel (never passed from host).
__global__ void wmax_kernel(const float* __restrict__ w, int which) {
    int e = blockIdx.y;
    int n = blockIdx.x * 256 + threadIdx.x;
    const float* src = w + (size_t)e * DDIM * HDIM + n;
    float m = 0.f;
    for (int k = 0; k < DDIM; k++) m = fmaxf(m, fabsf(src[(size_t)k * HDIM]));
    float* s_out = which ? g_sw2 : g_sw1;
    s_out[e * HDIM + n] = m / QS;
}

// w [E][K][N] fp32 -> [E][N][K] int8 hi/lo using per-(e,n) scales
__global__ void tq_kernel(const float* __restrict__ w, int which) {
    __shared__ float tile[32][33];
    int e = blockIdx.z;
    int n0 = blockIdx.x * 32, k0 = blockIdx.y * 32;
    const float* src = w + (size_t)e * DDIM * HDIM;
    const float* sw = which ? g_sw2 : g_sw1;
    int8_t* q1 = which ? g_w2q1 : g_w1q1;
    int8_t* q2 = which ? g_w2q2 : g_w1q2;
    int tx = threadIdx.x, ty = threadIdx.y;
#pragma unroll
    for (int i = 0; i < 4; i++) {
        int k = k0 + ty + i * 8;
        tile[ty + i * 8][tx] = src[(size_t)k * HDIM + n0 + tx];
    }
    __syncthreads();
#pragma unroll
    for (int i = 0; i < 4; i++) {
        int n = n0 + ty + i * 8;
        float s = sw[e * HDIM + n];
        float inv = (s > 0.f) ? 1.0f / s : 0.f;
        float v = tile[tx][ty + i * 8];
        int8_t h, l;
        q16split(v, inv, h, l);
        size_t o = ((size_t)e * HDIM + n) * DDIM + k0 + tx;
        q1[o] = h; q2[o] = l;
    }
}

// h1 fp16 -> per-row scale + int8 hi/lo. One warp per (e,slot) row.
__global__ void quant_h1() {
    int row = blockIdx.x * 8 + (threadIdx.x >> 5);
    int e = row >> 14;              // / NTOK
    int slot = row & (NTOK - 1);
    if (slot >= g_cnt[e]) return;
    int lane = threadIdx.x & 31;
    const uint4* src = (const uint4*)(g_h1f + (size_t)row * HDIM);
    uint4 v[8];
    float m = 0.f;
#pragma unroll
    for (int j = 0; j < 8; j++) {
        v[j] = src[lane + j * 32];
        const __half2* h2 = (const __half2*)&v[j];
#pragma unroll
        for (int q = 0; q < 4; q++) {
            float2 f = __half22float2(h2[q]);
            m = fmaxf(m, fmaxf(fabsf(f.x), fabsf(f.y)));
        }
    }
#pragma unroll
    for (int o = 16; o; o >>= 1) m = fmaxf(m, __shfl_xor_sync(0xffffffffu, m, o));
    float s = m / QS;
    float inv = (m > 0.f) ? QS / m : 0.f;
    if (lane == 0) g_sh1[row] = s;
    uint2* p1 = (uint2*)(g_h1q1 + (size_t)row * HDIM);
    uint2* p2 = (uint2*)(g_h1q2 + (size_t)row * HDIM);
#pragma unroll
    for (int j = 0; j < 8; j++) {
        const __half2* h2 = (const __half2*)&v[j];
        uint32_t hw[2] = {0, 0}, lw[2] = {0, 0};
#pragma unroll
        for (int q = 0; q < 4; q++) {
            float2 f = __half22float2(h2[q]);
            int8_t ha, la, hb, lb;
            q16split(f.x, inv, ha, la);
            q16split(f.y, inv, hb, lb);
            hw[q >> 1] |= ((uint32_t)(uint8_t)ha | ((uint32_t)(uint8_t)hb << 8)) << ((q & 1) * 16);
            lw[q >> 1] |= ((uint32_t)(uint8_t)la | ((uint32_t)(uint8_t)lb << 8)) << ((q & 1) * 16);
        }
        p1[lane + j * 32] = make_uint2(hw[0], hw[1]);
        p2[lane + j * 32] = make_uint2(lw[0], lw[1]);
    }
}

// ---------------------------------------------------------------------------
// Router (records rank of each slot: 0 = primary, 1 = secondary)
// ---------------------------------------------------------------------------
__global__ void router_kernel(const float* __restrict__ x,
                              const float* __restrict__ gw) {
    int warp = (blockIdx.x * blockDim.x + threadIdx.x) >> 5;
    int lane = threadIdx.x & 31;
    if (warp >= NTOK) return;
    const float* xr = x + (size_t)warp * DDIM;
    float a0 = 0.f, a1 = 0.f, a2 = 0.f, a3 = 0.f;
    for (int k = lane; k < DDIM; k += 32) {
        float xv = xr[k];
        a0 = fmaf(xv, gw[k], a0);
        a1 = fmaf(xv, gw[DDIM + k], a1);
        a2 = fmaf(xv, gw[2 * DDIM + k], a2);
        a3 = fmaf(xv, gw[3 * DDIM + k], a3);
    }
#pragma unroll
    for (int o = 16; o; o >>= 1) {
        a0 += __shfl_xor_sync(0xffffffffu, a0, o);
        a1 += __shfl_xor_sync(0xffffffffu, a1, o);
        a2 += __shfl_xor_sync(0xffffffffu, a2, o);
        a3 += __shfl_xor_sync(0xffffffffu, a3, o);
    }
    if (lane == 0) {
        float l[4] = {a0, a1, a2, a3};
        int i0 = 0;
#pragma unroll
        for (int e = 1; e < 4; e++) if (l[e] > l[i0]) i0 = e;
        int i1 = (i0 == 0) ? 1 : 0;
#pragma unroll
        for (int e = 0; e < 4; e++) if (e != i0 && l[e] > l[i1]) i1 = e;
        float w0 = 1.0f / (1.0f + expf(l[i1] - l[i0]));
        float w1 = 1.0f - w0;
        int s0 = atomicAdd(&g_cnt[i0], 1);
        g_tok[i0][s0] = warp; g_wgt[i0][s0] = w0; g_rank[i0][s0] = 0;
        int s1 = atomicAdd(&g_cnt[i1], 1);
        g_tok[i1][s1] = warp; g_wgt[i1][s1] = w1; g_rank[i1][s1] = 1;
    }
}

// ---------------------------------------------------------------------------
// int8 GEMM core: 3-term limb product, m16n8k32, 64x32 warp tile (4mt x 4nt)
// ---------------------------------------------------------------------------
__device__ __forceinline__ void compute_chunk_i8(uint32_t base, int wm, int wn,
                                                 int lane, int acc1[4][4][4],
                                                 int acc2[4][4][4]) {
    uint32_t A1 = base, A2 = base + TILE, B1 = base + 2 * TILE, B2 = base + 3 * TILE;
    uint32_t a_row  = (uint32_t)(wm * 64) + (lane & 15);
    uint32_t a_kb   = (uint32_t)((lane >> 4) << 4);
    uint32_t b_row0 = (uint32_t)(wn * 32) + (((lane >> 4) & 1) << 3) + (lane & 7);
    uint32_t b_kb   = (uint32_t)(((lane >> 3) & 1) << 4);

#pragma unroll
    for (int s = 0; s < 4; s++) {
        uint32_t boff = s * 32;
        uint32_t a1f[4][4], a2f[4][4];
#pragma unroll
        for (int mt = 0; mt < 4; mt++) {
            uint32_t off = swz(a_row + mt * 16, boff + a_kb);
            ldsm_x4(a1f[mt], A1 + off);
            ldsm_x4(a2f[mt], A2 + off);
        }
#pragma unroll
        for (int p = 0; p < 2; p++) {
            uint32_t off = swz(b_row0 + p * 16, boff + b_kb);
            uint32_t r1[4], r2[4];
            ldsm_x4(r1, B1 + off);
            ldsm_x4(r2, B2 + off);
#pragma unroll
            for (int mt = 0; mt < 4; mt++) {
                imma(acc1[mt][2 * p],     a1f[mt], r1);
                imma(acc1[mt][2 * p + 1], a1f[mt], r1 + 2);
                imma(acc2[mt][2 * p],     a1f[mt], r2);
                imma(acc2[mt][2 * p + 1], a1f[mt], r2 + 2);
                imma(acc2[mt][2 * p],     a2f[mt], r1);
                imma(acc2[mt][2 * p + 1], a2f[mt], r1 + 2);
            }
        }
    }
}

// ---------------------------------------------------------------------------
// GEMM1: h1[e][m][:] = gelu(x[tok] @ w1[e] + b1[e]) -> fp16
// ---------------------------------------------------------------------------
__global__ void __launch_bounds__(256, 1)
moe_gemm1(const float* __restrict__ b1) {
    int e = blockIdx.z;
    int cnt = g_cnt[e];
    int m0 = blockIdx.y * BM;
    if (m0 >= cnt) return;
    int n0 = blockIdx.x * BN;

    __shared__ int   s_tok[BM];
    __shared__ float s_sa[BM];
    extern __shared__ char dynsm[];
    uint32_t ab = (smem_u32(dynsm) + 1023) & ~1023u;

    int tid = threadIdx.x;
    int wid = tid >> 5, lane = tid & 31;
    int wm = wid & 1, wn = wid >> 1;

    if (tid < BM) {
        int s = m0 + tid; if (s > cnt - 1) s = cnt - 1;
        int t = g_tok[e][s];
        s_tok[tid] = t;
        s_sa[tid] = g_sx[t];
    }
    __syncthreads();

    const int8_t* wq1 = g_w1q1 + (size_t)e * HDIM * DDIM;
    const int8_t* wq2 = g_w1q2 + (size_t)e * HDIM * DDIM;

    int acc1[4][4][4], acc2[4][4][4];
#pragma unroll
    for (int i = 0; i < 4; i++)
#pragma unroll
        for (int j = 0; j < 4; j++)
#pragma unroll
            for (int k = 0; k < 4; k++) { acc1[i][j][k] = 0; acc2[i][j][k] = 0; }

    int r = tid >> 3, c16 = tid & 7;
    auto load_chunk = [&](int c, uint32_t bufb) {
        int k0 = c * 128;
#pragma unroll
        for (int i = 0; i < 4; i++) {
            int rr = r + i * 32;
            uint32_t so = swz((uint32_t)rr, (uint32_t)(c16 * 16));
            size_t go = (size_t)s_tok[rr] * DDIM + k0 + c16 * 16;
            cp16(ab + bufb + so, g_x1 + go);
            cp16(ab + bufb + TILE + so, g_x2 + go);
            size_t gb = (size_t)(n0 + rr) * DDIM + k0 + c16 * 16;
            cp16(ab + bufb + 2 * TILE + so, wq1 + gb);
            cp16(ab + bufb + 3 * TILE + so, wq2 + gb);
        }
        CP_COMMIT();
    };

    load_chunk(0, 0);
    load_chunk(1, STAGE);
    for (int c = 0; c < NCH; c++) {
        if (c + 1 < NCH) CP_WAIT1(); else CP_WAIT0();
        __syncthreads();
        compute_chunk_i8(ab + (uint32_t)(c % NSTG) * STAGE, wm, wn, lane, acc1, acc2);
        if (c + 2 < NCH) load_chunk(c + 2, (uint32_t)((c + 2) % NSTG) * STAGE);
    }

    // Epilogue: dequant + bias + exact GELU -> fp16
    int g = lane >> 2, tig = lane & 3;
    __half* h1f = g_h1f + (size_t)e * NTOK * HDIM;
    const float* bias = b1 + (size_t)e * HDIM;
#pragma unroll
    for (int nt = 0; nt < 4; nt++) {
        int n = n0 + wn * 32 + nt * 8 + tig * 2;
        float sb0 = g_sw1[e * HDIM + n], sb1 = g_sw1[e * HDIM + n + 1];
        float bv0 = bias[n], bv1 = bias[n + 1];
#pragma unroll
        for (int mt = 0; mt < 4; mt++) {
#pragma unroll
            for (int half = 0; half < 2; half++) {
                int rl = wm * 64 + mt * 16 + g + half * 8;
                int m = m0 + rl;
                if (m < cnt) {
                    float sa = s_sa[rl];
                    float c0 = fmaf(65536.f, (float)acc1[mt][nt][half * 2],
                                    256.f * (float)acc2[mt][nt][half * 2]);
                    float c1 = fmaf(65536.f, (float)acc1[mt][nt][half * 2 + 1],
                                    256.f * (float)acc2[mt][nt][half * 2 + 1]);
                    float v0 = sa * sb0 * c0 + bv0;
                    float v1 = sa * sb1 * c1 + bv1;
                    float g0 = 0.5f * v0 * (1.0f + erff(v0 * 0.70710678118654752f));
                    float g1 = 0.5f * v1 * (1.0f + erff(v1 * 0.70710678118654752f));
                    __half2 hv = __floats2half2_rn(g0, g1);
                    *(__half2*)(h1f + (size_t)m * HDIM + n) = hv;
                }
            }
        }
    }
}

// ---------------------------------------------------------------------------
// GEMM2: g_outr[rank][tok][:] = wgt * (h1[e] @ w2[e] + b2[e])
// ---------------------------------------------------------------------------
__global__ void __launch_bounds__(256, 1)
moe_gemm2(const float* __restrict__ b2) {
    int e = blockIdx.z;
    int cnt = g_cnt[e];
    int m0 = blockIdx.y * BM;
    if (m0 >= cnt) return;
    int n0 = blockIdx.x * BN;

    __shared__ int   s_tok[BM];
    __shared__ float s_wgt[BM];
    __shared__ int   s_rnk[BM];
    __shared__ float s_sa[BM];
    extern __shared__ char dynsm[];
    uint32_t ab = (smem_u32(dynsm) + 1023) & ~1023u;

    int tid = threadIdx.x;
    int wid = tid >> 5, lane = tid & 31;
    int wm = wid & 1, wn = wid >> 1;

    if (tid < BM) {
        int s = m0 + tid; if (s > cnt - 1) s = cnt - 1;
        s_tok[tid] = g_tok[e][s];
        s_wgt[tid] = g_wgt[e][s];
        s_rnk[tid] = g_rank[e][s];
        s_sa[tid] = g_sh1[e * NTOK + s];
    }
    __syncthreads();

    const int8_t* aq1 = g_h1q1 + (size_t)e * NTOK * HDIM;
    const int8_t* aq2 = g_h1q2 + (size_t)e * NTOK * HDIM;
    const int8_t* wq1 = g_w2q1 + (size_t)e * HDIM * HDIM;
    const int8_t* wq2 = g_w2q2 + (size_t)e * HDIM * HDIM;

    int acc1[4][4][4], acc2[4][4][4];
#pragma unroll
    for (int i = 0; i < 4; i++)
#pragma unroll
        for (int j = 0; j < 4; j++)
#pragma unroll
            for (int k = 0; k < 4; k++) { acc1[i][j][k] = 0; acc2[i][j][k] = 0; }

    int r = tid >> 3, c16 = tid & 7;
    auto load_chunk = [&](int c, uint32_t bufb) {
        int k0 = c * 128;
#pragma unroll
        for (int i = 0; i < 4; i++) {
            int rr = r + i * 32;
            uint32_t so = swz((uint32_t)rr, (uint32_t)(c16 * 16));
            int mm = m0 + rr; if (mm > cnt - 1) mm = cnt - 1;
            size_t go = (size_t)mm * HDIM + k0 + c16 * 16;
            cp16(ab + bufb + so, aq1 + go);
            cp16(ab + bufb + TILE + so, aq2 + go);
            size_t gb = (size_t)(n0 + rr) * HDIM + k0 + c16 * 16;
            cp16(ab + bufb + 2 * TILE + so, wq1 + gb);
            cp16(ab + bufb + 3 * TILE + so, wq2 + gb);
        }
        CP_COMMIT();
    };

    load_chunk(0, 0);
    load_chunk(1, STAGE);
    for (int c = 0; c < NCH; c++) {
        if (c + 1 < NCH) CP_WAIT1(); else CP_WAIT0();
        __syncthreads();
        compute_chunk_i8(ab + (uint32_t)(c % NSTG) * STAGE, wm, wn, lane, acc1, acc2);
        if (c + 2 < NCH) load_chunk(c + 2, (uint32_t)((c + 2) % NSTG) * STAGE);
    }

    // Epilogue: dequant + bias, * wgt -> plain store into rank plane
    int g = lane >> 2, tig = lane & 3;
    const float* bias = b2 + (size_t)e * HDIM;
#pragma unroll
    for (int nt = 0; nt < 4; nt++) {
        int n = n0 + wn * 32 + nt * 8 + tig * 2;
        float sb0 = g_sw2[e * HDIM + n], sb1 = g_sw2[e * HDIM + n + 1];
        float bv0 = bias[n], bv1 = bias[n + 1];
#pragma unroll
        for (int mt = 0; mt < 4; mt++) {
#pragma unroll
            for (int half = 0; half < 2; half++) {
                int rl = wm * 64 + mt * 16 + g + half * 8;
                int m = m0 + rl;
                if (m < cnt) {
                    float sa = s_sa[rl];
                    float w = s_wgt[rl];
                    float c0 = fmaf(65536.f, (float)acc1[mt][nt][half * 2],
                                    256.f * (float)acc2[mt][nt][half * 2]);
                    float c1 = fmaf(65536.f, (float)acc1[mt][nt][half * 2 + 1],
                                    256.f * (float)acc2[mt][nt][half * 2 + 1]);
                    float* dst = g_outr[s_rnk[rl]] + (size_t)s_tok[rl] * HDIM + n;
                    dst[0] = w * (sa * sb0 * c0 + bv0);
                    dst[1] = w * (sa * sb1 * c1 + bv1);
                }
            }
        }
    }
}

// ---------------------------------------------------------------------------
__global__ void combine_kernel(float4* __restrict__ out, long n4) {
    long i = (long)blockIdx.x * blockDim.x + threadIdx.x;
    long st = (long)gridDim.x * blockDim.x;
    const float4* r0 = (const float4*)g_outr[0];
    const float4* r1 = (const float4*)g_outr[1];
    for (; i < n4; i += st) {
        float4 a = r0[i], b = r1[i];
        out[i] = make_float4(a.x + b.x, a.y + b.y, a.z + b.z, a.w + b.w);
    }
}

// ---------------------------------------------------------------------------
extern "C" void kernel_launch(void* const* d_in, const int* in_sizes, int n_in,
                              void* d_out, int out_size) {
    const float* x  = (const float*)d_in[0];
    const float* gw = (const float*)d_in[1];
    const float* w1 = (const float*)d_in[2];
    const float* b1 = (const float*)d_in[3];
    const float* w2 = (const float*)d_in[4];
    const float* b2 = (const float*)d_in[5];
    float* out = (float*)d_out;

    cudaFuncSetAttribute(moe_gemm1, cudaFuncAttributeMaxDynamicSharedMemorySize, SMEM_TOTAL);
    cudaFuncSetAttribute(moe_gemm2, cudaFuncAttributeMaxDynamicSharedMemorySize, SMEM_TOTAL);

    reset_kernel<<<1, 32>>>();
    quant_x<<<NTOK / 8, 256>>>(x);
    wmax_kernel<<<dim3(HDIM / 256, NEXP), 256>>>(w1, 0);
    wmax_kernel<<<dim3(HDIM / 256, NEXP), 256>>>(w2, 1);
    tq_kernel<<<dim3(64, 64, NEXP), dim3(32, 8)>>>(w1, 0);
    tq_kernel<<<dim3(64, 64, NEXP), dim3(32, 8)>>>(w2, 1);
    router_kernel<<<NTOK / 8, 256>>>(x, gw);

    moe_gemm1<<<dim3(HDIM / BN, NTOK / BM, NEXP), 256, SMEM_TOTAL>>>(b1);
    quant_h1<<<NEXP * NTOK / 8, 256>>>();
    moe_gemm2<<<dim3(HDIM / BN, NTOK / BM, NEXP), 256, SMEM_TOTAL>>>(b2);
    combine_kernel<<<2048, 256>>>((float4*)out, (long)out_size / 4);
}

// round 8
// speedup vs baseline: 2.8769x; 2.8769x over previous
#include <cuda_runtime.h>
#include <cuda_bf16.h>
#include <math.h>
#include <stdint.h>

// Problem constants (B=8, S=2048, D=2048, H=2048, E=4, TOP_K=2)
#define NTOK 16384
#define DDIM 2048
#define HDIM 2048
#define NEXP 4
#define NCH  32              // gemm1: K/64 chunks

// gemm1 tile config (proven R5): 128M x 256N CTA, 64x64 warp tiles
#define BM 128
#define BN 256
#define BK 64
#define TILE_A 16384
#define TILE_B 32768
#define STAGE_BYTES (2 * TILE_A + 2 * TILE_B)   // 98304
#define SMEM_TOTAL (1024 + 2 * STAGE_BYTES)     // 197632

// gemm2 tile config (2 CTAs/SM): 128M x 128N, 64x32 warp tiles, BK=32
#define BN2 128
#define TILE2 8192                               // 128 rows x 64B packed
#define STAGE2 (4 * TILE2)                       // 32768
#define NCH2 64
#define SMEM2 (1024 + 2 * STAGE2)                // 66560

// ---------------------------------------------------------------------------
// Scratch (static device arrays — no runtime allocation)
// ---------------------------------------------------------------------------
__device__ int   g_cnt[NEXP];
__device__ int   g_tok[NEXP][NTOK];
__device__ float g_wgt[NEXP][NTOK];
__device__ int   g_rank[NEXP][NTOK];

__device__ __nv_bfloat16 g_xh[(size_t)NTOK * DDIM];
__device__ __nv_bfloat16 g_xl[(size_t)NTOK * DDIM];
__device__ __nv_bfloat16 g_w1h[(size_t)NEXP * HDIM * DDIM];  // [e][n][k]
__device__ __nv_bfloat16 g_w1l[(size_t)NEXP * HDIM * DDIM];
__device__ __nv_bfloat16 g_w2h[(size_t)NEXP * HDIM * HDIM];  // [e][n][k]
__device__ __nv_bfloat16 g_w2l[(size_t)NEXP * HDIM * HDIM];
__device__ __nv_bfloat16 g_h1h[(size_t)NEXP * NTOK * HDIM];  // [e][slot][k]
__device__ __nv_bfloat16 g_h1l[(size_t)NEXP * NTOK * HDIM];
__device__ float g_outr[2][(size_t)NTOK * HDIM];             // rank-split partials

// ---------------------------------------------------------------------------
// Helpers
// ---------------------------------------------------------------------------
__device__ __forceinline__ uint32_t smem_u32(const void* p) {
    uint32_t a;
    asm("{ .reg .u64 t; cvta.to.shared.u64 t, %1; cvt.u32.u64 %0, t; }"
        : "=r"(a) : "l"(p));
    return a;
}
// 128B-row XOR swizzle (gemm1 tiles)
__device__ __forceinline__ uint32_t swz(uint32_t row, uint32_t byteoff) {
    uint32_t c16 = byteoff >> 4, lo = byteoff & 15;
    return row * 128 + (((c16 ^ (row & 7)) & 7) << 4) + lo;
}
// 64B-row conflict-free packing into 128B lines (gemm2 tiles):
// line = row/2; slot = (row&1)*4 | ((c16 + line) & 3)  -> 8 distinct slots
// across the 8 rows of any ldmatrix m8n8 access.
__device__ __forceinline__ uint32_t swz32(uint32_t row, uint32_t byteoff) {
    uint32_t c16 = byteoff >> 4, lo = byteoff & 15;
    uint32_t line = row >> 1;
    uint32_t slot = ((row & 1) << 2) | ((c16 + line) & 3);
    return line * 128 + slot * 16 + lo;
}
__device__ __forceinline__ void cp16(uint32_t saddr, const void* gaddr) {
    asm volatile("cp.async.cg.shared.global [%0], [%1], 16;" :: "r"(saddr), "l"(gaddr));
}
#define CP_COMMIT() asm volatile("cp.async.commit_group;" ::: "memory")
#define CP_WAIT0()  asm volatile("cp.async.wait_group 0;" ::: "memory")
#define CP_WAIT1()  asm volatile("cp.async.wait_group 1;" ::: "memory")

__device__ __forceinline__ void ldsm_x4(uint32_t* r, uint32_t addr) {
    asm volatile("ldmatrix.sync.aligned.m8n8.x4.shared.b16 {%0,%1,%2,%3}, [%4];"
        : "=r"(r[0]), "=r"(r[1]), "=r"(r[2]), "=r"(r[3]) : "r"(addr));
}
__device__ __forceinline__ void mma16816(float* d, const uint32_t* a, const uint32_t* b) {
    asm volatile(
        "mma.sync.aligned.m16n8k16.row.col.f32.bf16.bf16.f32 "
        "{%0,%1,%2,%3}, {%4,%5,%6,%7}, {%8,%9}, {%0,%1,%2,%3};"
        : "+f"(d[0]), "+f"(d[1]), "+f"(d[2]), "+f"(d[3])
        : "r"(a[0]), "r"(a[1]), "r"(a[2]), "r"(a[3]), "r"(b[0]), "r"(b[1]));
}

// ---------------------------------------------------------------------------
__global__ void reset_kernel() {
    if (threadIdx.x < NEXP) g_cnt[threadIdx.x] = 0;
}

// Fused: x fp32 -> bf16 hi/lo planes AND router (top-2 + renorm + lists).
// One warp per token: single pass over the row.
__global__ void prep_x(const float* __restrict__ x, const float* __restrict__ gw) {
    int tok = blockIdx.x * 8 + (threadIdx.x >> 5);
    int lane = threadIdx.x & 31;
    const float4* src = (const float4*)(x + (size_t)tok * DDIM);
    const float4* g4 = (const float4*)gw;
    __nv_bfloat162* xh2 = (__nv_bfloat162*)(g_xh + (size_t)tok * DDIM);
    __nv_bfloat162* xl2 = (__nv_bfloat162*)(g_xl + (size_t)tok * DDIM);

    float a0 = 0.f, a1 = 0.f, a2 = 0.f, a3 = 0.f;
#pragma unroll
    for (int j = 0; j < 16; j++) {
        int k4 = lane + j * 32;
        float4 v = src[k4];
        float4 w0 = g4[k4], w1 = g4[512 + k4], w2 = g4[1024 + k4], w3 = g4[1536 + k4];
        a0 = fmaf(v.x, w0.x, fmaf(v.y, w0.y, fmaf(v.z, w0.z, fmaf(v.w, w0.w, a0))));
        a1 = fmaf(v.x, w1.x, fmaf(v.y, w1.y, fmaf(v.z, w1.z, fmaf(v.w, w1.w, a1))));
        a2 = fmaf(v.x, w2.x, fmaf(v.y, w2.y, fmaf(v.z, w2.z, fmaf(v.w, w2.w, a2))));
        a3 = fmaf(v.x, w3.x, fmaf(v.y, w3.y, fmaf(v.z, w3.z, fmaf(v.w, w3.w, a3))));
        __nv_bfloat16 h0 = __float2bfloat16(v.x), h1 = __float2bfloat16(v.y);
        __nv_bfloat16 h2 = __float2bfloat16(v.z), h3 = __float2bfloat16(v.w);
        __nv_bfloat16 l0 = __float2bfloat16(v.x - __bfloat162float(h0));
        __nv_bfloat16 l1 = __float2bfloat16(v.y - __bfloat162float(h1));
        __nv_bfloat16 l2 = __float2bfloat16(v.z - __bfloat162float(h2));
        __nv_bfloat16 l3 = __float2bfloat16(v.w - __bfloat162float(h3));
        xh2[2 * k4]     = __nv_bfloat162(h0, h1);
        xh2[2 * k4 + 1] = __nv_bfloat162(h2, h3);
        xl2[2 * k4]     = __nv_bfloat162(l0, l1);
        xl2[2 * k4 + 1] = __nv_bfloat162(l2, l3);
    }
#pragma unroll
    for (int o = 16; o; o >>= 1) {
        a0 += __shfl_xor_sync(0xffffffffu, a0, o);
        a1 += __shfl_xor_sync(0xffffffffu, a1, o);
        a2 += __shfl_xor_sync(0xffffffffu, a2, o);
        a3 += __shfl_xor_sync(0xffffffffu, a3, o);
    }
    if (lane == 0) {
        float l[4] = {a0, a1, a2, a3};
        int i0 = 0;
#pragma unroll
        for (int e = 1; e < 4; e++) if (l[e] > l[i0]) i0 = e;
        int i1 = (i0 == 0) ? 1 : 0;
#pragma unroll
        for (int e = 0; e < 4; e++) if (e != i0 && l[e] > l[i1]) i1 = e;
        float w0 = 1.0f / (1.0f + expf(l[i1] - l[i0]));
        float w1 = 1.0f - w0;
        int s0 = atomicAdd(&g_cnt[i0], 1);
        g_tok[i0][s0] = tok; g_wgt[i0][s0] = w0; g_rank[i0][s0] = 0;
        int s1 = atomicAdd(&g_cnt[i1], 1);
        g_tok[i1][s1] = tok; g_wgt[i1][s1] = w1; g_rank[i1][s1] = 1;
    }
}

// w [E][K][N] fp32 -> wt [E][N][K] bf16 hi/lo (K = N = 2048)
__global__ void transpose_w(const float* __restrict__ w, int which) {
    __shared__ float tile[32][33];
    int e = blockIdx.z;
    int n0 = blockIdx.x * 32, k0 = blockIdx.y * 32;
    const float* src = w + (size_t)e * DDIM * HDIM;
    int tx = threadIdx.x, ty = threadIdx.y;
#pragma unroll
    for (int i = 0; i < 4; i++) {
        int k = k0 + ty + i * 8;
        tile[ty + i * 8][tx] = src[(size_t)k * HDIM + n0 + tx];
    }
    __syncthreads();
    __nv_bfloat16* oh = which ? g_w2h : g_w1h;
    __nv_bfloat16* ol = which ? g_w2l : g_w1l;
#pragma unroll
    for (int i = 0; i < 4; i++) {
        int n = n0 + ty + i * 8;
        float v = tile[tx][ty + i * 8];
        __nv_bfloat16 h = __float2bfloat16(v);
        __nv_bfloat16 l = __float2bfloat16(v - __bfloat162float(h));
        size_t o = ((size_t)e * HDIM + n) * DDIM + k0 + tx;
        oh[o] = h; ol[o] = l;
    }
}

// ---------------------------------------------------------------------------
// GEMM1 core (R5-proven): bf16x3, m16n8k16, ldmatrix, 64x64 warp tiles
// ---------------------------------------------------------------------------
__device__ __forceinline__ void compute_chunk(uint32_t base, int wm, int wn,
                                              int lane, float acc[4][8][4]) {
    uint32_t aH = base;
    uint32_t aL = base + TILE_A;
    uint32_t bH = base + 2 * TILE_A;
    uint32_t bL = base + 2 * TILE_A + TILE_B;

    uint32_t a_row  = (uint32_t)(wm * 64) + (lane & 15);
    uint32_t a_kb   = (uint32_t)((lane >> 4) << 4);
    uint32_t b_row0 = (uint32_t)(wn * 64) + (((lane >> 4) & 1) << 3) + (lane & 7);
    uint32_t b_kb   = (uint32_t)(((lane >> 3) & 1) << 4);

#pragma unroll
    for (int s = 0; s < 4; s++) {
        uint32_t boff = s * 32;
        uint32_t ah[4][4], al[4][4];
#pragma unroll
        for (int mt = 0; mt < 4; mt++) {
            uint32_t off = swz(a_row + mt * 16, boff + a_kb);
            ldsm_x4(ah[mt], aH + off);
            ldsm_x4(al[mt], aL + off);
        }
#pragma unroll
        for (int p = 0; p < 4; p++) {
            uint32_t off = swz(b_row0 + p * 16, boff + b_kb);
            uint32_t rh[4], rl[4];
            ldsm_x4(rh, bH + off);
            ldsm_x4(rl, bL + off);
#pragma unroll
            for (int mt = 0; mt < 4; mt++) {
                mma16816(acc[mt][2 * p],     ah[mt], rh);
                mma16816(acc[mt][2 * p + 1], ah[mt], rh + 2);
                mma16816(acc[mt][2 * p],     ah[mt], rl);
                mma16816(acc[mt][2 * p + 1], ah[mt], rl + 2);
                mma16816(acc[mt][2 * p],     al[mt], rh);
                mma16816(acc[mt][2 * p + 1], al[mt], rh + 2);
            }
        }
    }
}

// ---------------------------------------------------------------------------
// GEMM1: h1[e][m][:] = gelu(x[tok] @ w1[e] + b1[e]) -> bf16 hi/lo (unchanged)
// ---------------------------------------------------------------------------
__global__ void __launch_bounds__(256, 1)
moe_gemm1(const float* __restrict__ b1) {
    int e = blockIdx.z;
    int cnt = g_cnt[e];
    int m0 = blockIdx.y * BM;
    if (m0 >= cnt) return;
    int n0 = blockIdx.x * BN;

    __shared__ int s_tok[BM];
    extern __shared__ char dynsm[];
    uint32_t ab = (smem_u32(dynsm) + 1023) & ~1023u;

    int tid = threadIdx.x;
    int wid = tid >> 5, lane = tid & 31;
    int wm = wid & 1, wn = wid >> 1;

    if (tid < BM) {
        int s = m0 + tid; if (s > cnt - 1) s = cnt - 1;
        s_tok[tid] = g_tok[e][s];
    }
    __syncthreads();

    const __nv_bfloat16* wh = g_w1h + (size_t)e * HDIM * DDIM;
    const __nv_bfloat16* wl = g_w1l + (size_t)e * HDIM * DDIM;

    float acc[4][8][4];
#pragma unroll
    for (int i = 0; i < 4; i++)
#pragma unroll
        for (int j = 0; j < 8; j++)
#pragma unroll
            for (int k = 0; k < 4; k++) acc[i][j][k] = 0.f;

    int r = tid >> 3, c16 = tid & 7;
    auto load_chunk = [&](int c, uint32_t bufb) {
        int k0 = c * BK;
#pragma unroll
        for (int i = 0; i < 4; i++) {
            int rr = r + i * 32;
            uint32_t so = swz((uint32_t)rr, (uint32_t)(c16 * 16));
            size_t go = (size_t)s_tok[rr] * DDIM + k0 + c16 * 8;
            cp16(ab + bufb + so, g_xh + go);
            cp16(ab + bufb + TILE_A + so, g_xl + go);
        }
#pragma unroll
        for (int i = 0; i < 8; i++) {
            int rr = r + i * 32;
            uint32_t so = swz((uint32_t)rr, (uint32_t)(c16 * 16));
            size_t gb = (size_t)(n0 + rr) * DDIM + k0 + c16 * 8;
            cp16(ab + bufb + 2 * TILE_A + so, wh + gb);
            cp16(ab + bufb + 2 * TILE_A + TILE_B + so, wl + gb);
        }
        CP_COMMIT();
    };

    load_chunk(0, 0);
    for (int c = 0; c < NCH; c++) {
        if (c + 1 < NCH) {
            load_chunk(c + 1, (uint32_t)((c + 1) & 1) * STAGE_BYTES);
            CP_WAIT1();
        } else {
            CP_WAIT0();
        }
        __syncthreads();
        compute_chunk(ab + (uint32_t)(c & 1) * STAGE_BYTES, wm, wn, lane, acc);
        __syncthreads();
    }

    // Epilogue: bias + exact GELU -> bf16 hi/lo -> global
    int g = lane >> 2, tig = lane & 3;
    __nv_bfloat16* h1h = g_h1h + (size_t)e * NTOK * HDIM;
    __nv_bfloat16* h1l = g_h1l + (size_t)e * NTOK * HDIM;
    const float* bias = b1 + (size_t)e * HDIM;
#pragma unroll
    for (int nt = 0; nt < 8; nt++) {
        int n = n0 + wn * 64 + nt * 8 + tig * 2;
        float bv0 = bias[n], bv1 = bias[n + 1];
#pragma unroll
        for (int mt = 0; mt < 4; mt++) {
#pragma unroll
            for (int half = 0; half < 2; half++) {
                int m = m0 + wm * 64 + mt * 16 + g + half * 8;
                if (m < cnt) {
                    float v0 = acc[mt][nt][half * 2 + 0] + bv0;
                    float v1 = acc[mt][nt][half * 2 + 1] + bv1;
                    float g0 = 0.5f * v0 * (1.0f + erff(v0 * 0.70710678118654752f));
                    float g1 = 0.5f * v1 * (1.0f + erff(v1 * 0.70710678118654752f));
                    __nv_bfloat16 h0 = __float2bfloat16(g0);
                    __nv_bfloat16 h1 = __float2bfloat16(g1);
                    __nv_bfloat16 l0 = __float2bfloat16(g0 - __bfloat162float(h0));
                    __nv_bfloat16 l1 = __float2bfloat16(g1 - __bfloat162float(h1));
                    uint32_t hp = (uint32_t)__bfloat16_as_ushort(h0) |
                                  ((uint32_t)__bfloat16_as_ushort(h1) << 16);
                    uint32_t lp = (uint32_t)__bfloat16_as_ushort(l0) |
                                  ((uint32_t)__bfloat16_as_ushort(l1) << 16);
                    *(uint32_t*)(h1h + (size_t)m * HDIM + n) = hp;
                    *(uint32_t*)(h1l + (size_t)m * HDIM + n) = lp;
                }
            }
        }
    }
}

// ---------------------------------------------------------------------------
// GEMM2 (NEW, 2 CTAs/SM): g_outr[rank][tok][:] = wgt * (h1[e] @ w2[e] + b2[e])
// 128x128 tile, 64x32 warp tiles, BK=32 packed 64B rows, occupancy 2.
// ---------------------------------------------------------------------------
__global__ void __launch_bounds__(256, 2)
moe_gemm2(const float* __restrict__ b2) {
    int e = blockIdx.z;
    int cnt = g_cnt[e];
    int m0 = blockIdx.y * BM;
    if (m0 >= cnt) return;
    int n0 = blockIdx.x * BN2;

    __shared__ int   s_tok[BM];
    __shared__ float s_wgt[BM];
    __shared__ int   s_rnk[BM];
    extern __shared__ char dynsm[];
    uint32_t ab = (smem_u32(dynsm) + 1023) & ~1023u;

    int tid = threadIdx.x;
    int wid = tid >> 5, lane = tid & 31;
    int wm = wid & 1, wn = wid >> 1;

    if (tid < BM) {
        int s = m0 + tid; if (s > cnt - 1) s = cnt - 1;
        s_tok[tid] = g_tok[e][s];
        s_wgt[tid] = g_wgt[e][s];
        s_rnk[tid] = g_rank[e][s];
    }
    __syncthreads();

    const __nv_bfloat16* ah = g_h1h + (size_t)e * NTOK * HDIM;
    const __nv_bfloat16* al = g_h1l + (size_t)e * NTOK * HDIM;
    const __nv_bfloat16* wh = g_w2h + (size_t)e * HDIM * HDIM;
    const __nv_bfloat16* wl = g_w2l + (size_t)e * HDIM * HDIM;

    float acc[4][4][4];
#pragma unroll
    for (int i = 0; i < 4; i++)
#pragma unroll
        for (int j = 0; j < 4; j++)
#pragma unroll
            for (int k = 0; k < 4; k++) acc[i][j][k] = 0.f;

    auto load_chunk = [&](int c, uint32_t bufb) {
        int k0 = c * 32;
#pragma unroll
        for (int i = 0; i < 2; i++) {
            int id = tid + i * 256;
            int row = id >> 2, c16 = id & 3;
            uint32_t so = swz32((uint32_t)row, (uint32_t)(c16 * 16));
            int mm = m0 + row; if (mm > cnt - 1) mm = cnt - 1;
            size_t ga = (size_t)mm * HDIM + k0 + c16 * 8;
            cp16(ab + bufb + so, ah + ga);
            cp16(ab + bufb + TILE2 + so, al + ga);
            size_t gb = (size_t)(n0 + row) * HDIM + k0 + c16 * 8;
            cp16(ab + bufb + 2 * TILE2 + so, wh + gb);
            cp16(ab + bufb + 3 * TILE2 + so, wl + gb);
        }
        CP_COMMIT();
    };

    uint32_t a_row  = (uint32_t)(wm * 64) + (lane & 15);
    uint32_t a_kb   = (uint32_t)((lane >> 4) << 4);
    uint32_t b_row0 = (uint32_t)(wn * 32) + (((lane >> 4) & 1) << 3) + (lane & 7);
    uint32_t b_kb   = (uint32_t)(((lane >> 3) & 1) << 4);

    load_chunk(0, 0);
    load_chunk(1, STAGE2);
    for (int c = 0; c < NCH2; c++) {
        if (c + 1 < NCH2) CP_WAIT1(); else CP_WAIT0();
        __syncthreads();
        uint32_t base = ab + (uint32_t)(c & 1) * STAGE2;
        uint32_t A1 = base, A2 = base + TILE2;
        uint32_t B1 = base + 2 * TILE2, B2 = base + 3 * TILE2;
#pragma unroll
        for (int s = 0; s < 2; s++) {
            uint32_t boff = s * 32;
            uint32_t bh[2][4], bl[2][4];
#pragma unroll
            for (int p = 0; p < 2; p++) {
                uint32_t off = swz32(b_row0 + p * 16, boff + b_kb);
                ldsm_x4(bh[p], B1 + off);
                ldsm_x4(bl[p], B2 + off);
            }
#pragma unroll
            for (int mt = 0; mt < 4; mt++) {
                uint32_t ahf[4], alf[4];
                uint32_t off = swz32(a_row + mt * 16, boff + a_kb);
                ldsm_x4(ahf, A1 + off);
                ldsm_x4(alf, A2 + off);
#pragma unroll
                for (int nt = 0; nt < 4; nt++) {
                    const uint32_t* bhp = bh[nt >> 1] + (nt & 1) * 2;
                    const uint32_t* blp = bl[nt >> 1] + (nt & 1) * 2;
                    mma16816(acc[mt][nt], ahf, bhp);
                    mma16816(acc[mt][nt], ahf, blp);
                    mma16816(acc[mt][nt], alf, bhp);
                }
            }
        }
        __syncthreads();
        if (c + 2 < NCH2) load_chunk(c + 2, (uint32_t)((c + 2) & 1) * STAGE2);
    }

    // Epilogue: (acc + b2) * wgt -> plain store into rank plane
    int g = lane >> 2, tig = lane & 3;
    const float* bias = b2 + (size_t)e * HDIM;
#pragma unroll
    for (int nt = 0; nt < 4; nt++) {
        int n = n0 + wn * 32 + nt * 8 + tig * 2;
        float bv0 = bias[n], bv1 = bias[n + 1];
#pragma unroll
        for (int mt = 0; mt < 4; mt++) {
#pragma unroll
            for (int half = 0; half < 2; half++) {
                int rl = wm * 64 + mt * 16 + g + half * 8;
                int m = m0 + rl;
                if (m < cnt) {
                    float w = s_wgt[rl];
                    float* dst = g_outr[s_rnk[rl]] + (size_t)s_tok[rl] * HDIM + n;
                    dst[0] = w * (acc[mt][nt][half * 2 + 0] + bv0);
                    dst[1] = w * (acc[mt][nt][half * 2 + 1] + bv1);
                }
            }
        }
    }
}

// ---------------------------------------------------------------------------
__global__ void combine_kernel(float4* __restrict__ out, long n4) {
    long i = (long)blockIdx.x * blockDim.x + threadIdx.x;
    long st = (long)gridDim.x * blockDim.x;
    const float4* r0 = (const float4*)g_outr[0];
    const float4* r1 = (const float4*)g_outr[1];
    for (; i < n4; i += st) {
        float4 a = r0[i], b = r1[i];
        out[i] = make_float4(a.x + b.x, a.y + b.y, a.z + b.z, a.w + b.w);
    }
}

// ---------------------------------------------------------------------------
extern "C" void kernel_launch(void* const* d_in, const int* in_sizes, int n_in,
                              void* d_out, int out_size) {
    const float* x  = (const float*)d_in[0];
    const float* gw = (const float*)d_in[1];
    const float* w1 = (const float*)d_in[2];
    const float* b1 = (const float*)d_in[3];
    const float* w2 = (const float*)d_in[4];
    const float* b2 = (const float*)d_in[5];
    float* out = (float*)d_out;

    cudaFuncSetAttribute(moe_gemm1, cudaFuncAttributeMaxDynamicSharedMemorySize, SMEM_TOTAL);
    cudaFuncSetAttribute(moe_gemm2, cudaFuncAttributeMaxDynamicSharedMemorySize, SMEM2);

    reset_kernel<<<1, 32>>>();
    prep_x<<<NTOK / 8, 256>>>(x, gw);
    transpose_w<<<dim3(64, 64, 4), dim3(32, 8)>>>(w1, 0);
    transpose_w<<<dim3(64, 64, 4), dim3(32, 8)>>>(w2, 1);

    moe_gemm1<<<dim3(HDIM / BN, NTOK / BM, NEXP), 256, SMEM_TOTAL>>>(b1);
    moe_gemm2<<<dim3(HDIM / BN2, NTOK / BM, NEXP), 256, SMEM2>>>(b2);
    combine_kernel<<<2048, 256>>>((float4*)out, (long)out_size / 4);
}

// round 9
// speedup vs baseline: 4.4154x; 1.5348x over previous
#include <cuda_runtime.h>
#include <cuda_fp16.h>
#include <math.h>
#include <stdint.h>

// Problem constants (B=8, S=2048, D=2048, H=2048, E=4, TOP_K=2)
#define NTOK 16384
#define DDIM 2048
#define HDIM 2048
#define NEXP 4
#define NCH  32              // K/64 chunks

// Tile config (R5-proven): 128M x 256N CTA, 64x64 warp tiles (8 warps: 2M x 4N)
#define BM 128
#define BN 256
#define BK 64
#define TILE_A 16384                        // 128 rows x 128B (64 fp16)
#define TILE_B 32768                        // 256 rows x 128B
#define STAGE_BYTES (TILE_A + 2 * TILE_B)   // A | Bh | Bl = 81920
#define SMEM_TOTAL (1024 + 2 * STAGE_BYTES) // 164864

// ---------------------------------------------------------------------------
// Scratch (static device arrays — no runtime allocation)
// ---------------------------------------------------------------------------
__device__ int   g_cnt[NEXP];
__device__ int   g_tok[NEXP][NTOK];
__device__ float g_wgt[NEXP][NTOK];
__device__ int   g_rank[NEXP][NTOK];

__device__ __align__(16) __half g_xf[(size_t)NTOK * DDIM];          // x fp16
__device__ __align__(16) __half g_w1h[(size_t)NEXP * HDIM * DDIM];  // [e][n][k] hi
__device__ __align__(16) __half g_w1l[(size_t)NEXP * HDIM * DDIM];  // lo limb
__device__ __align__(16) __half g_w2h[(size_t)NEXP * HDIM * HDIM];
__device__ __align__(16) __half g_w2l[(size_t)NEXP * HDIM * HDIM];
__device__ __align__(16) __half g_h1f[(size_t)NEXP * NTOK * HDIM];  // gelu out fp16
__device__ __align__(16) float  g_outr[2][(size_t)NTOK * HDIM];     // rank-split

// ---------------------------------------------------------------------------
// Helpers
// ---------------------------------------------------------------------------
__device__ __forceinline__ uint32_t smem_u32(const void* p) {
    uint32_t a;
    asm("{ .reg .u64 t; cvta.to.shared.u64 t, %1; cvt.u32.u64 %0, t; }"
        : "=r"(a) : "l"(p));
    return a;
}
// 128B-row XOR swizzle
__device__ __forceinline__ uint32_t swz(uint32_t row, uint32_t byteoff) {
    uint32_t c16 = byteoff >> 4, lo = byteoff & 15;
    return row * 128 + (((c16 ^ (row & 7)) & 7) << 4) + lo;
}
__device__ __forceinline__ void cp16(uint32_t saddr, const void* gaddr) {
    asm volatile("cp.async.cg.shared.global [%0], [%1], 16;" :: "r"(saddr), "l"(gaddr));
}
#define CP_COMMIT() asm volatile("cp.async.commit_group;" ::: "memory")
#define CP_WAIT0()  asm volatile("cp.async.wait_group 0;" ::: "memory")
#define CP_WAIT1()  asm volatile("cp.async.wait_group 1;" ::: "memory")

__device__ __forceinline__ void ldsm_x4(uint32_t* r, uint32_t addr) {
    asm volatile("ldmatrix.sync.aligned.m8n8.x4.shared.b16 {%0,%1,%2,%3}, [%4];"
        : "=r"(r[0]), "=r"(r[1]), "=r"(r[2]), "=r"(r[3]) : "r"(addr));
}
__device__ __forceinline__ void mma_f16(float* d, const uint32_t* a, const uint32_t* b) {
    asm volatile(
        "mma.sync.aligned.m16n8k16.row.col.f32.f16.f16.f32 "
        "{%0,%1,%2,%3}, {%4,%5,%6,%7}, {%8,%9}, {%0,%1,%2,%3};"
        : "+f"(d[0]), "+f"(d[1]), "+f"(d[2]), "+f"(d[3])
        : "r"(a[0]), "r"(a[1]), "r"(a[2]), "r"(a[3]), "r"(b[0]), "r"(b[1]));
}

// ---------------------------------------------------------------------------
__global__ void reset_kernel() {
    if (threadIdx.x < NEXP) g_cnt[threadIdx.x] = 0;
}

// Fused: x fp32 -> fp16 plane AND router (top-2 + renorm + per-expert lists).
__global__ void prep_x(const float* __restrict__ x, const float* __restrict__ gw) {
    int tok = blockIdx.x * 8 + (threadIdx.x >> 5);
    int lane = threadIdx.x & 31;
    const float4* src = (const float4*)(x + (size_t)tok * DDIM);
    const float4* g4 = (const float4*)gw;
    uint2* xf = (uint2*)(g_xf + (size_t)tok * DDIM);

    float a0 = 0.f, a1 = 0.f, a2 = 0.f, a3 = 0.f;
#pragma unroll
    for (int j = 0; j < 16; j++) {
        int k4 = lane + j * 32;
        float4 v = src[k4];
        float4 w0 = g4[k4], w1 = g4[512 + k4], w2 = g4[1024 + k4], w3 = g4[1536 + k4];
        a0 = fmaf(v.x, w0.x, fmaf(v.y, w0.y, fmaf(v.z, w0.z, fmaf(v.w, w0.w, a0))));
        a1 = fmaf(v.x, w1.x, fmaf(v.y, w1.y, fmaf(v.z, w1.z, fmaf(v.w, w1.w, a1))));
        a2 = fmaf(v.x, w2.x, fmaf(v.y, w2.y, fmaf(v.z, w2.z, fmaf(v.w, w2.w, a2))));
        a3 = fmaf(v.x, w3.x, fmaf(v.y, w3.y, fmaf(v.z, w3.z, fmaf(v.w, w3.w, a3))));
        __half2 p0 = __floats2half2_rn(v.x, v.y);
        __half2 p1 = __floats2half2_rn(v.z, v.w);
        xf[k4] = make_uint2(*(uint32_t*)&p0, *(uint32_t*)&p1);
    }
#pragma unroll
    for (int o = 16; o; o >>= 1) {
        a0 += __shfl_xor_sync(0xffffffffu, a0, o);
        a1 += __shfl_xor_sync(0xffffffffu, a1, o);
        a2 += __shfl_xor_sync(0xffffffffu, a2, o);
        a3 += __shfl_xor_sync(0xffffffffu, a3, o);
    }
    if (lane == 0) {
        float l[4] = {a0, a1, a2, a3};
        int i0 = 0;
#pragma unroll
        for (int e = 1; e < 4; e++) if (l[e] > l[i0]) i0 = e;
        int i1 = (i0 == 0) ? 1 : 0;
#pragma unroll
        for (int e = 0; e < 4; e++) if (e != i0 && l[e] > l[i1]) i1 = e;
        float w0 = 1.0f / (1.0f + expf(l[i1] - l[i0]));
        float w1 = 1.0f - w0;
        int s0 = atomicAdd(&g_cnt[i0], 1);
        g_tok[i0][s0] = tok; g_wgt[i0][s0] = w0; g_rank[i0][s0] = 0;
        int s1 = atomicAdd(&g_cnt[i1], 1);
        g_tok[i1][s1] = tok; g_wgt[i1][s1] = w1; g_rank[i1][s1] = 1;
    }
}

// w [E][K][N] fp32 -> wt [E][N][K] fp16 hi/lo (K = N = 2048)
__global__ void transpose_w(const float* __restrict__ w, int which) {
    __shared__ float tile[32][33];
    int e = blockIdx.z;
    int n0 = blockIdx.x * 32, k0 = blockIdx.y * 32;
    const float* src = w + (size_t)e * DDIM * HDIM;
    int tx = threadIdx.x, ty = threadIdx.y;
#pragma unroll
    for (int i = 0; i < 4; i++) {
        int k = k0 + ty + i * 8;
        tile[ty + i * 8][tx] = src[(size_t)k * HDIM + n0 + tx];
    }
    __syncthreads();
    __half* oh = which ? g_w2h : g_w1h;
    __half* ol = which ? g_w2l : g_w1l;
#pragma unroll
    for (int i = 0; i < 4; i++) {
        int n = n0 + ty + i * 8;
        float v = tile[tx][ty + i * 8];
        __half h = __float2half_rn(v);
        __half l = __float2half_rn(v - __half2float(h));
        size_t o = ((size_t)e * HDIM + n) * DDIM + k0 + tx;
        oh[o] = h; ol[o] = l;
    }
}

// ---------------------------------------------------------------------------
// GEMM core: fp16 2-term (A x Bh + A x Bl), m16n8k16, ldmatrix, 64x64 warp tile
// ---------------------------------------------------------------------------
__device__ __forceinline__ void compute_chunk(uint32_t base, int wm, int wn,
                                              int lane, float acc[4][8][4]) {
    uint32_t aF = base;
    uint32_t bH = base + TILE_A;
    uint32_t bL = base + TILE_A + TILE_B;

    uint32_t a_row  = (uint32_t)(wm * 64) + (lane & 15);
    uint32_t a_kb   = (uint32_t)((lane >> 4) << 4);
    uint32_t b_row0 = (uint32_t)(wn * 64) + (((lane >> 4) & 1) << 3) + (lane & 7);
    uint32_t b_kb   = (uint32_t)(((lane >> 3) & 1) << 4);

#pragma unroll
    for (int s = 0; s < 4; s++) {
        uint32_t boff = s * 32;
        uint32_t af[4][4];
#pragma unroll
        for (int mt = 0; mt < 4; mt++)
            ldsm_x4(af[mt], aF + swz(a_row + mt * 16, boff + a_kb));
#pragma unroll
        for (int p = 0; p < 4; p++) {          // p covers n-tiles 2p, 2p+1
            uint32_t off = swz(b_row0 + p * 16, boff + b_kb);
            uint32_t rh[4], rl[4];
            ldsm_x4(rh, bH + off);
            ldsm_x4(rl, bL + off);
#pragma unroll
            for (int mt = 0; mt < 4; mt++) {
                mma_f16(acc[mt][2 * p],     af[mt], rh);
                mma_f16(acc[mt][2 * p + 1], af[mt], rh + 2);
                mma_f16(acc[mt][2 * p],     af[mt], rl);
                mma_f16(acc[mt][2 * p + 1], af[mt], rl + 2);
            }
        }
    }
}

// ---------------------------------------------------------------------------
// GEMM1: h1[e][m][:] = gelu(x[tok] @ w1[e] + b1[e]) -> fp16
// ---------------------------------------------------------------------------
__global__ void __launch_bounds__(256, 1)
moe_gemm1(const float* __restrict__ b1) {
    int e = blockIdx.z;
    int cnt = g_cnt[e];
    int m0 = blockIdx.y * BM;
    if (m0 >= cnt) return;
    int n0 = blockIdx.x * BN;

    __shared__ int s_tok[BM];
    extern __shared__ char dynsm[];
    uint32_t ab = (smem_u32(dynsm) + 1023) & ~1023u;

    int tid = threadIdx.x;
    int wid = tid >> 5, lane = tid & 31;
    int wm = wid & 1, wn = wid >> 1;

    if (tid < BM) {
        int s = m0 + tid; if (s > cnt - 1) s = cnt - 1;
        s_tok[tid] = g_tok[e][s];
    }
    __syncthreads();

    const __half* wh = g_w1h + (size_t)e * HDIM * DDIM;
    const __half* wl = g_w1l + (size_t)e * HDIM * DDIM;

    float acc[4][8][4];
#pragma unroll
    for (int i = 0; i < 4; i++)
#pragma unroll
        for (int j = 0; j < 8; j++)
#pragma unroll
            for (int k = 0; k < 4; k++) acc[i][j][k] = 0.f;

    int r = tid >> 3, c16 = tid & 7;
    auto load_chunk = [&](int c, uint32_t bufb) {
        int k0 = c * BK;
#pragma unroll
        for (int i = 0; i < 4; i++) {           // A: 128 rows, 1 plane
            int rr = r + i * 32;
            uint32_t so = swz((uint32_t)rr, (uint32_t)(c16 * 16));
            cp16(ab + bufb + so, g_xf + (size_t)s_tok[rr] * DDIM + k0 + c16 * 8);
        }
#pragma unroll
        for (int i = 0; i < 8; i++) {           // B: 256 rows, 2 planes
            int rr = r + i * 32;
            uint32_t so = swz((uint32_t)rr, (uint32_t)(c16 * 16));
            size_t gb = (size_t)(n0 + rr) * DDIM + k0 + c16 * 8;
            cp16(ab + bufb + TILE_A + so, wh + gb);
            cp16(ab + bufb + TILE_A + TILE_B + so, wl + gb);
        }
        CP_COMMIT();
    };

    load_chunk(0, 0);
    for (int c = 0; c < NCH; c++) {
        if (c + 1 < NCH) {
            load_chunk(c + 1, (uint32_t)((c + 1) & 1) * STAGE_BYTES);
            CP_WAIT1();
        } else {
            CP_WAIT0();
        }
        __syncthreads();
        compute_chunk(ab + (uint32_t)(c & 1) * STAGE_BYTES, wm, wn, lane, acc);
        __syncthreads();
    }

    // Epilogue: bias + exact GELU -> fp16
    int g = lane >> 2, tig = lane & 3;
    __half* h1f = g_h1f + (size_t)e * NTOK * HDIM;
    const float* bias = b1 + (size_t)e * HDIM;
#pragma unroll
    for (int nt = 0; nt < 8; nt++) {
        int n = n0 + wn * 64 + nt * 8 + tig * 2;
        float bv0 = bias[n], bv1 = bias[n + 1];
#pragma unroll
        for (int mt = 0; mt < 4; mt++) {
#pragma unroll
            for (int half = 0; half < 2; half++) {
                int m = m0 + wm * 64 + mt * 16 + g + half * 8;
                if (m < cnt) {
                    float v0 = acc[mt][nt][half * 2 + 0] + bv0;
                    float v1 = acc[mt][nt][half * 2 + 1] + bv1;
                    float g0 = 0.5f * v0 * (1.0f + erff(v0 * 0.70710678118654752f));
                    float g1 = 0.5f * v1 * (1.0f + erff(v1 * 0.70710678118654752f));
                    __half2 hv = __floats2half2_rn(g0, g1);
                    *(uint32_t*)(h1f + (size_t)m * HDIM + n) = *(uint32_t*)&hv;
                }
            }
        }
    }
}

// ---------------------------------------------------------------------------
// GEMM2: g_outr[rank][tok][:] = wgt * (h1[e] @ w2[e] + b2[e])  (R5 config)
// ---------------------------------------------------------------------------
__global__ void __launch_bounds__(256, 1)
moe_gemm2(const float* __restrict__ b2) {
    int e = blockIdx.z;
    int cnt = g_cnt[e];
    int m0 = blockIdx.y * BM;
    if (m0 >= cnt) return;
    int n0 = blockIdx.x * BN;

    __shared__ int   s_tok[BM];
    __shared__ float s_wgt[BM];
    __shared__ int   s_rnk[BM];
    extern __shared__ char dynsm[];
    uint32_t ab = (smem_u32(dynsm) + 1023) & ~1023u;

    int tid = threadIdx.x;
    int wid = tid >> 5, lane = tid & 31;
    int wm = wid & 1, wn = wid >> 1;

    if (tid < BM) {
        int s = m0 + tid; if (s > cnt - 1) s = cnt - 1;
        s_tok[tid] = g_tok[e][s];
        s_wgt[tid] = g_wgt[e][s];
        s_rnk[tid] = g_rank[e][s];
    }
    __syncthreads();

    const __half* ahp = g_h1f + (size_t)e * NTOK * HDIM;
    const __half* wh = g_w2h + (size_t)e * HDIM * HDIM;
    const __half* wl = g_w2l + (size_t)e * HDIM * HDIM;

    float acc[4][8][4];
#pragma unroll
    for (int i = 0; i < 4; i++)
#pragma unroll
        for (int j = 0; j < 8; j++)
#pragma unroll
            for (int k = 0; k < 4; k++) acc[i][j][k] = 0.f;

    int r = tid >> 3, c16 = tid & 7;
    auto load_chunk = [&](int c, uint32_t bufb) {
        int k0 = c * BK;
#pragma unroll
        for (int i = 0; i < 4; i++) {
            int rr = r + i * 32;
            uint32_t so = swz((uint32_t)rr, (uint32_t)(c16 * 16));
            int mm = m0 + rr; if (mm > cnt - 1) mm = cnt - 1;
            cp16(ab + bufb + so, ahp + (size_t)mm * HDIM + k0 + c16 * 8);
        }
#pragma unroll
        for (int i = 0; i < 8; i++) {
            int rr = r + i * 32;
            uint32_t so = swz((uint32_t)rr, (uint32_t)(c16 * 16));
            size_t gb = (size_t)(n0 + rr) * HDIM + k0 + c16 * 8;
            cp16(ab + bufb + TILE_A + so, wh + gb);
            cp16(ab + bufb + TILE_A + TILE_B + so, wl + gb);
        }
        CP_COMMIT();
    };

    load_chunk(0, 0);
    for (int c = 0; c < NCH; c++) {
        if (c + 1 < NCH) {
            load_chunk(c + 1, (uint32_t)((c + 1) & 1) * STAGE_BYTES);
            CP_WAIT1();
        } else {
            CP_WAIT0();
        }
        __syncthreads();
        compute_chunk(ab + (uint32_t)(c & 1) * STAGE_BYTES, wm, wn, lane, acc);
        __syncthreads();
    }

    // Epilogue: (acc + b2) * wgt -> plain store into rank plane
    int g = lane >> 2, tig = lane & 3;
    const float* bias = b2 + (size_t)e * HDIM;
#pragma unroll
    for (int nt = 0; nt < 8; nt++) {
        int n = n0 + wn * 64 + nt * 8 + tig * 2;
        float bv0 = bias[n], bv1 = bias[n + 1];
#pragma unroll
        for (int mt = 0; mt < 4; mt++) {
#pragma unroll
            for (int half = 0; half < 2; half++) {
                int rl = wm * 64 + mt * 16 + g + half * 8;
                int m = m0 + rl;
                if (m < cnt) {
                    float w = s_wgt[rl];
                    float* dst = g_outr[s_rnk[rl]] + (size_t)s_tok[rl] * HDIM + n;
                    dst[0] = w * (acc[mt][nt][half * 2 + 0] + bv0);
                    dst[1] = w * (acc[mt][nt][half * 2 + 1] + bv1);
                }
            }
        }
    }
}

// ---------------------------------------------------------------------------
__global__ void combine_kernel(float4* __restrict__ out, long n4) {
    long i = (long)blockIdx.x * blockDim.x + threadIdx.x;
    long st = (long)gridDim.x * blockDim.x;
    const float4* r0 = (const float4*)g_outr[0];
    const float4* r1 = (const float4*)g_outr[1];
    for (; i < n4; i += st) {
        float4 a = r0[i], b = r1[i];
        out[i] = make_float4(a.x + b.x, a.y + b.y, a.z + b.z, a.w + b.w);
    }
}

// ---------------------------------------------------------------------------
extern "C" void kernel_launch(void* const* d_in, const int* in_sizes, int n_in,
                              void* d_out, int out_size) {
    const float* x  = (const float*)d_in[0];
    const float* gw = (const float*)d_in[1];
    const float* w1 = (const float*)d_in[2];
    const float* b1 = (const float*)d_in[3];
    const float* w2 = (const float*)d_in[4];
    const float* b2 = (const float*)d_in[5];
    float* out = (float*)d_out;

    cudaFuncSetAttribute(moe_gemm1, cudaFuncAttributeMaxDynamicSharedMemorySize, SMEM_TOTAL);
    cudaFuncSetAttribute(moe_gemm2, cudaFuncAttributeMaxDynamicSharedMemorySize, SMEM_TOTAL);

    reset_kernel<<<1, 32>>>();
    prep_x<<<NTOK / 8, 256>>>(x, gw);
    transpose_w<<<dim3(64, 64, 4), dim3(32, 8)>>>(w1, 0);
    transpose_w<<<dim3(64, 64, 4), dim3(32, 8)>>>(w2, 1);

    moe_gemm1<<<dim3(HDIM / BN, NTOK / BM, NEXP), 256, SMEM_TOTAL>>>(b1);
    moe_gemm2<<<dim3(HDIM / BN, NTOK / BM, NEXP), 256, SMEM_TOTAL>>>(b2);
    combine_kernel<<<2048, 256>>>((float4*)out, (long)out_size / 4);
}

// round 10
// speedup vs baseline: 7.3748x; 1.6703x over previous
#include <cuda_runtime.h>
#include <cuda_fp16.h>
#include <math.h>
#include <stdint.h>

// Problem constants (B=8, S=2048, D=2048, H=2048, E=4, TOP_K=2)
#define NTOK 16384
#define DDIM 2048
#define HDIM 2048
#define NEXP 4
#define NCH  32              // K/64 chunks

// Tile config: 128M x 256N CTA, 64x64 warp tiles (8 warps: 2M x 4N)
#define BM 128
#define BN 256
#define BK 64
#define TILE_A 16384                        // 128 rows x 128B (64 fp16)
#define TILE_B 32768                        // 256 rows x 128B
#define STAGE_BYTES (TILE_A + TILE_B)       // A | B = 49152
#define NSTG 3
#define SMEM_TOTAL (1024 + NSTG * STAGE_BYTES) // 148480

// ---------------------------------------------------------------------------
// Scratch (static device arrays — no runtime allocation)
// ---------------------------------------------------------------------------
__device__ int   g_cnt[NEXP];
__device__ int   g_tok[NEXP][NTOK];
__device__ float g_wgt[NEXP][NTOK];
__device__ int   g_rank[NEXP][NTOK];

__device__ __align__(16) __half g_xf[(size_t)NTOK * DDIM];          // x fp16
__device__ __align__(16) __half g_w1f[(size_t)NEXP * HDIM * DDIM];  // [e][n][k]
__device__ __align__(16) __half g_w2f[(size_t)NEXP * HDIM * HDIM];
__device__ __align__(16) __half g_h1f[(size_t)NEXP * NTOK * HDIM];  // gelu out fp16
__device__ __align__(16) float  g_outr[2][(size_t)NTOK * HDIM];     // rank-split

// ---------------------------------------------------------------------------
// Helpers
// ---------------------------------------------------------------------------
__device__ __forceinline__ uint32_t smem_u32(const void* p) {
    uint32_t a;
    asm("{ .reg .u64 t; cvta.to.shared.u64 t, %1; cvt.u32.u64 %0, t; }"
        : "=r"(a) : "l"(p));
    return a;
}
// 128B-row XOR swizzle
__device__ __forceinline__ uint32_t swz(uint32_t row, uint32_t byteoff) {
    uint32_t c16 = byteoff >> 4, lo = byteoff & 15;
    return row * 128 + (((c16 ^ (row & 7)) & 7) << 4) + lo;
}
__device__ __forceinline__ void cp16(uint32_t saddr, const void* gaddr) {
    asm volatile("cp.async.cg.shared.global [%0], [%1], 16;" :: "r"(saddr), "l"(gaddr));
}
#define CP_COMMIT() asm volatile("cp.async.commit_group;" ::: "memory")
#define CP_WAIT0()  asm volatile("cp.async.wait_group 0;" ::: "memory")
#define CP_WAIT1()  asm volatile("cp.async.wait_group 1;" ::: "memory")

__device__ __forceinline__ void ldsm_x4(uint32_t* r, uint32_t addr) {
    asm volatile("ldmatrix.sync.aligned.m8n8.x4.shared.b16 {%0,%1,%2,%3}, [%4];"
        : "=r"(r[0]), "=r"(r[1]), "=r"(r[2]), "=r"(r[3]) : "r"(addr));
}
__device__ __forceinline__ void mma_f16(float* d, const uint32_t* a, const uint32_t* b) {
    asm volatile(
        "mma.sync.aligned.m16n8k16.row.col.f32.f16.f16.f32 "
        "{%0,%1,%2,%3}, {%4,%5,%6,%7}, {%8,%9}, {%0,%1,%2,%3};"
        : "+f"(d[0]), "+f"(d[1]), "+f"(d[2]), "+f"(d[3])
        : "r"(a[0]), "r"(a[1]), "r"(a[2]), "r"(a[3]), "r"(b[0]), "r"(b[1]));
}

// ---------------------------------------------------------------------------
__global__ void reset_kernel() {
    if (threadIdx.x < NEXP) g_cnt[threadIdx.x] = 0;
}

// Fused: x fp32 -> fp16 plane AND router (top-2 + renorm + per-expert lists).
__global__ void prep_x(const float* __restrict__ x, const float* __restrict__ gw) {
    int tok = blockIdx.x * 8 + (threadIdx.x >> 5);
    int lane = threadIdx.x & 31;
    const float4* src = (const float4*)(x + (size_t)tok * DDIM);
    const float4* g4 = (const float4*)gw;
    uint2* xf = (uint2*)(g_xf + (size_t)tok * DDIM);

    float a0 = 0.f, a1 = 0.f, a2 = 0.f, a3 = 0.f;
#pragma unroll
    for (int j = 0; j < 16; j++) {
        int k4 = lane + j * 32;
        float4 v = src[k4];
        float4 w0 = g4[k4], w1 = g4[512 + k4], w2 = g4[1024 + k4], w3 = g4[1536 + k4];
        a0 = fmaf(v.x, w0.x, fmaf(v.y, w0.y, fmaf(v.z, w0.z, fmaf(v.w, w0.w, a0))));
        a1 = fmaf(v.x, w1.x, fmaf(v.y, w1.y, fmaf(v.z, w1.z, fmaf(v.w, w1.w, a1))));
        a2 = fmaf(v.x, w2.x, fmaf(v.y, w2.y, fmaf(v.z, w2.z, fmaf(v.w, w2.w, a2))));
        a3 = fmaf(v.x, w3.x, fmaf(v.y, w3.y, fmaf(v.z, w3.z, fmaf(v.w, w3.w, a3))));
        __half2 p0 = __floats2half2_rn(v.x, v.y);
        __half2 p1 = __floats2half2_rn(v.z, v.w);
        xf[k4] = make_uint2(*(uint32_t*)&p0, *(uint32_t*)&p1);
    }
#pragma unroll
    for (int o = 16; o; o >>= 1) {
        a0 += __shfl_xor_sync(0xffffffffu, a0, o);
        a1 += __shfl_xor_sync(0xffffffffu, a1, o);
        a2 += __shfl_xor_sync(0xffffffffu, a2, o);
        a3 += __shfl_xor_sync(0xffffffffu, a3, o);
    }
    if (lane == 0) {
        float l[4] = {a0, a1, a2, a3};
        int i0 = 0;
#pragma unroll
        for (int e = 1; e < 4; e++) if (l[e] > l[i0]) i0 = e;
        int i1 = (i0 == 0) ? 1 : 0;
#pragma unroll
        for (int e = 0; e < 4; e++) if (e != i0 && l[e] > l[i1]) i1 = e;
        float w0 = 1.0f / (1.0f + expf(l[i1] - l[i0]));
        float w1 = 1.0f - w0;
        int s0 = atomicAdd(&g_cnt[i0], 1);
        g_tok[i0][s0] = tok; g_wgt[i0][s0] = w0; g_rank[i0][s0] = 0;
        int s1 = atomicAdd(&g_cnt[i1], 1);
        g_tok[i1][s1] = tok; g_wgt[i1][s1] = w1; g_rank[i1][s1] = 1;
    }
}

// w [E][K][N] fp32 -> wt [E][N][K] fp16 (K = N = 2048)
__global__ void transpose_w(const float* __restrict__ w, int which) {
    __shared__ float tile[32][33];
    int e = blockIdx.z;
    int n0 = blockIdx.x * 32, k0 = blockIdx.y * 32;
    const float* src = w + (size_t)e * DDIM * HDIM;
    int tx = threadIdx.x, ty = threadIdx.y;
#pragma unroll
    for (int i = 0; i < 4; i++) {
        int k = k0 + ty + i * 8;
        tile[ty + i * 8][tx] = src[(size_t)k * HDIM + n0 + tx];
    }
    __syncthreads();
    __half* of = which ? g_w2f : g_w1f;
#pragma unroll
    for (int i = 0; i < 4; i++) {
        int n = n0 + ty + i * 8;
        float v = tile[tx][ty + i * 8];
        size_t o = ((size_t)e * HDIM + n) * DDIM + k0 + tx;
        of[o] = __float2half_rn(v);
    }
}

// ---------------------------------------------------------------------------
// GEMM core: fp16 single-term, m16n8k16, ldmatrix, 64x64 warp tile
// ---------------------------------------------------------------------------
__device__ __forceinline__ void compute_chunk(uint32_t base, int wm, int wn,
                                              int lane, float acc[4][8][4]) {
    uint32_t aF = base;
    uint32_t bF = base + TILE_A;

    uint32_t a_row  = (uint32_t)(wm * 64) + (lane & 15);
    uint32_t a_kb   = (uint32_t)((lane >> 4) << 4);
    uint32_t b_row0 = (uint32_t)(wn * 64) + (((lane >> 4) & 1) << 3) + (lane & 7);
    uint32_t b_kb   = (uint32_t)(((lane >> 3) & 1) << 4);

#pragma unroll
    for (int s = 0; s < 4; s++) {
        uint32_t boff = s * 32;
        uint32_t af[4][4];
#pragma unroll
        for (int mt = 0; mt < 4; mt++)
            ldsm_x4(af[mt], aF + swz(a_row + mt * 16, boff + a_kb));
#pragma unroll
        for (int p = 0; p < 4; p++) {          // p covers n-tiles 2p, 2p+1
            uint32_t rb[4];
            ldsm_x4(rb, bF + swz(b_row0 + p * 16, boff + b_kb));
#pragma unroll
            for (int mt = 0; mt < 4; mt++) {
                mma_f16(acc[mt][2 * p],     af[mt], rb);
                mma_f16(acc[mt][2 * p + 1], af[mt], rb + 2);
            }
        }
    }
}

// ---------------------------------------------------------------------------
// GEMM1: h1[e][m][:] = gelu(x[tok] @ w1[e] + b1[e]) -> fp16
// ---------------------------------------------------------------------------
__global__ void __launch_bounds__(256, 1)
moe_gemm1(const float* __restrict__ b1) {
    int e = blockIdx.z;
    int cnt = g_cnt[e];
    int m0 = blockIdx.y * BM;
    if (m0 >= cnt) return;
    int n0 = blockIdx.x * BN;

    __shared__ int s_tok[BM];
    extern __shared__ char dynsm[];
    uint32_t ab = (smem_u32(dynsm) + 1023) & ~1023u;

    int tid = threadIdx.x;
    int wid = tid >> 5, lane = tid & 31;
    int wm = wid & 1, wn = wid >> 1;

    if (tid < BM) {
        int s = m0 + tid; if (s > cnt - 1) s = cnt - 1;
        s_tok[tid] = g_tok[e][s];
    }
    __syncthreads();

    const __half* wf = g_w1f + (size_t)e * HDIM * DDIM;

    float acc[4][8][4];
#pragma unroll
    for (int i = 0; i < 4; i++)
#pragma unroll
        for (int j = 0; j < 8; j++)
#pragma unroll
            for (int k = 0; k < 4; k++) acc[i][j][k] = 0.f;

    int r = tid >> 3, c16 = tid & 7;
    auto load_chunk = [&](int c, uint32_t bufb) {
        int k0 = c * BK;
#pragma unroll
        for (int i = 0; i < 4; i++) {           // A: 128 rows
            int rr = r + i * 32;
            uint32_t so = swz((uint32_t)rr, (uint32_t)(c16 * 16));
            cp16(ab + bufb + so, g_xf + (size_t)s_tok[rr] * DDIM + k0 + c16 * 8);
        }
#pragma unroll
        for (int i = 0; i < 8; i++) {           // B: 256 rows
            int rr = r + i * 32;
            uint32_t so = swz((uint32_t)rr, (uint32_t)(c16 * 16));
            cp16(ab + bufb + TILE_A + so, wf + (size_t)(n0 + rr) * DDIM + k0 + c16 * 8);
        }
        CP_COMMIT();
    };

    load_chunk(0, 0);
    load_chunk(1, STAGE_BYTES);
    for (int c = 0; c < NCH; c++) {
        if (c + 1 < NCH) CP_WAIT1(); else CP_WAIT0();
        __syncthreads();
        compute_chunk(ab + (uint32_t)(c % NSTG) * STAGE_BYTES, wm, wn, lane, acc);
        if (c + 2 < NCH) load_chunk(c + 2, (uint32_t)((c + 2) % NSTG) * STAGE_BYTES);
    }

    // Epilogue: bias + exact GELU -> fp16
    int g = lane >> 2, tig = lane & 3;
    __half* h1f = g_h1f + (size_t)e * NTOK * HDIM;
    const float* bias = b1 + (size_t)e * HDIM;
#pragma unroll
    for (int nt = 0; nt < 8; nt++) {
        int n = n0 + wn * 64 + nt * 8 + tig * 2;
        float bv0 = bias[n], bv1 = bias[n + 1];
#pragma unroll
        for (int mt = 0; mt < 4; mt++) {
#pragma unroll
            for (int half = 0; half < 2; half++) {
                int m = m0 + wm * 64 + mt * 16 + g + half * 8;
                if (m < cnt) {
                    float v0 = acc[mt][nt][half * 2 + 0] + bv0;
                    float v1 = acc[mt][nt][half * 2 + 1] + bv1;
                    float g0 = 0.5f * v0 * (1.0f + erff(v0 * 0.70710678118654752f));
                    float g1 = 0.5f * v1 * (1.0f + erff(v1 * 0.70710678118654752f));
                    __half2 hv = __floats2half2_rn(g0, g1);
                    *(uint32_t*)(h1f + (size_t)m * HDIM + n) = *(uint32_t*)&hv;
                }
            }
        }
    }
}

// ---------------------------------------------------------------------------
// GEMM2: g_outr[rank][tok][:] = wgt * (h1[e] @ w2[e] + b2[e])
// ---------------------------------------------------------------------------
__global__ void __launch_bounds__(256, 1)
moe_gemm2(const float* __restrict__ b2) {
    int e = blockIdx.z;
    int cnt = g_cnt[e];
    int m0 = blockIdx.y * BM;
    if (m0 >= cnt) return;
    int n0 = blockIdx.x * BN;

    __shared__ int   s_tok[BM];
    __shared__ float s_wgt[BM];
    __shared__ int   s_rnk[BM];
    extern __shared__ char dynsm[];
    uint32_t ab = (smem_u32(dynsm) + 1023) & ~1023u;

    int tid = threadIdx.x;
    int wid = tid >> 5, lane = tid & 31;
    int wm = wid & 1, wn = wid >> 1;

    if (tid < BM) {
        int s = m0 + tid; if (s > cnt - 1) s = cnt - 1;
        s_tok[tid] = g_tok[e][s];
        s_wgt[tid] = g_wgt[e][s];
        s_rnk[tid] = g_rank[e][s];
    }
    __syncthreads();

    const __half* ahp = g_h1f + (size_t)e * NTOK * HDIM;
    const __half* wf = g_w2f + (size_t)e * HDIM * HDIM;

    float acc[4][8][4];
#pragma unroll
    for (int i = 0; i < 4; i++)
#pragma unroll
        for (int j = 0; j < 8; j++)
#pragma unroll
            for (int k = 0; k < 4; k++) acc[i][j][k] = 0.f;

    int r = tid >> 3, c16 = tid & 7;
    auto load_chunk = [&](int c, uint32_t bufb) {
        int k0 = c * BK;
#pragma unroll
        for (int i = 0; i < 4; i++) {
            int rr = r + i * 32;
            uint32_t so = swz((uint32_t)rr, (uint32_t)(c16 * 16));
            int mm = m0 + rr; if (mm > cnt - 1) mm = cnt - 1;
            cp16(ab + bufb + so, ahp + (size_t)mm * HDIM + k0 + c16 * 8);
        }
#pragma unroll
        for (int i = 0; i < 8; i++) {
            int rr = r + i * 32;
            uint32_t so = swz((uint32_t)rr, (uint32_t)(c16 * 16));
            cp16(ab + bufb + TILE_A + so, wf + (size_t)(n0 + rr) * HDIM + k0 + c16 * 8);
        }
        CP_COMMIT();
    };

    load_chunk(0, 0);
    load_chunk(1, STAGE_BYTES);
    for (int c = 0; c < NCH; c++) {
        if (c + 1 < NCH) CP_WAIT1(); else CP_WAIT0();
        __syncthreads();
        compute_chunk(ab + (uint32_t)(c % NSTG) * STAGE_BYTES, wm, wn, lane, acc);
        if (c + 2 < NCH) load_chunk(c + 2, (uint32_t)((c + 2) % NSTG) * STAGE_BYTES);
    }

    // Epilogue: (acc + b2) * wgt -> plain store into rank plane
    int g = lane >> 2, tig = lane & 3;
    const float* bias = b2 + (size_t)e * HDIM;
#pragma unroll
    for (int nt = 0; nt < 8; nt++) {
        int n = n0 + wn * 64 + nt * 8 + tig * 2;
        float bv0 = bias[n], bv1 = bias[n + 1];
#pragma unroll
        for (int mt = 0; mt < 4; mt++) {
#pragma unroll
            for (int half = 0; half < 2; half++) {
                int rl = wm * 64 + mt * 16 + g + half * 8;
                int m = m0 + rl;
                if (m < cnt) {
                    float w = s_wgt[rl];
                    float* dst = g_outr[s_rnk[rl]] + (size_t)s_tok[rl] * HDIM + n;
                    dst[0] = w * (acc[mt][nt][half * 2 + 0] + bv0);
                    dst[1] = w * (acc[mt][nt][half * 2 + 1] + bv1);
                }
            }
        }
    }
}

// ---------------------------------------------------------------------------
__global__ void combine_kernel(float4* __restrict__ out, long n4) {
    long i = (long)blockIdx.x * blockDim.x + threadIdx.x;
    long st = (long)gridDim.x * blockDim.x;
    const float4* r0 = (const float4*)g_outr[0];
    const float4* r1 = (const float4*)g_outr[1];
    for (; i < n4; i += st) {
        float4 a = r0[i], b = r1[i];
        out[i] = make_float4(a.x + b.x, a.y + b.y, a.z + b.z, a.w + b.w);
    }
}

// ---------------------------------------------------------------------------
extern "C" void kernel_launch(void* const* d_in, const int* in_sizes, int n_in,
                              void* d_out, int out_size) {
    const float* x  = (const float*)d_in[0];
    const float* gw = (const float*)d_in[1];
    const float* w1 = (const float*)d_in[2];
    const float* b1 = (const float*)d_in[3];
    const float* w2 = (const float*)d_in[4];
    const float* b2 = (const float*)d_in[5];
    float* out = (float*)d_out;

    cudaFuncSetAttribute(moe_gemm1, cudaFuncAttributeMaxDynamicSharedMemorySize, SMEM_TOTAL);
    cudaFuncSetAttribute(moe_gemm2, cudaFuncAttributeMaxDynamicSharedMemorySize, SMEM_TOTAL);

    reset_kernel<<<1, 32>>>();
    prep_x<<<NTOK / 8, 256>>>(x, gw);
    transpose_w<<<dim3(64, 64, 4), dim3(32, 8)>>>(w1, 0);
    transpose_w<<<dim3(64, 64, 4), dim3(32, 8)>>>(w2, 1);

    moe_gemm1<<<dim3(HDIM / BN, NTOK / BM, NEXP), 256, SMEM_TOTAL>>>(b1);
    moe_gemm2<<<dim3(HDIM / BN, NTOK / BM, NEXP), 256, SMEM_TOTAL>>>(b2);
    combine_kernel<<<2048, 256>>>((float4*)out, (long)out_size / 4);
}

// round 11
// speedup vs baseline: 7.4715x; 1.0131x over previous
#include <cuda_runtime.h>
#include <cuda_fp16.h>
#include <math.h>
#include <stdint.h>

// Problem constants (B=8, S=2048, D=2048, H=2048, E=4, TOP_K=2)
#define NTOK 16384
#define DDIM 2048
#define HDIM 2048
#define NEXP 4
#define NCH  32              // K/64 chunks

// Tile config: 128M x 256N CTA, 512 threads (16 warps: 4M x 4N, 32x64 warp tile)
#define BM 128
#define BN 256
#define BK 64
#define NTHREADS 512
#define TILE_A 16384                        // 128 rows x 128B (64 fp16)
#define TILE_B 32768                        // 256 rows x 128B
#define STAGE_BYTES (TILE_A + TILE_B)       // A | B = 49152
#define NSTG 3
#define SMEM_TOTAL (1024 + NSTG * STAGE_BYTES) // 148480

// ---------------------------------------------------------------------------
// Scratch (static device arrays — no runtime allocation)
// ---------------------------------------------------------------------------
__device__ int   g_cnt[NEXP];
__device__ int   g_tok[NEXP][NTOK];
__device__ float g_wgt[NEXP][NTOK];
__device__ int   g_rank[NEXP][NTOK];

__device__ __align__(16) __half g_xf[(size_t)NTOK * DDIM];          // x fp16
__device__ __align__(16) __half g_w1f[(size_t)NEXP * HDIM * DDIM];  // [e][n][k]
__device__ __align__(16) __half g_w2f[(size_t)NEXP * HDIM * HDIM];
__device__ __align__(16) __half g_h1f[(size_t)NEXP * NTOK * HDIM];  // gelu out fp16
__device__ __align__(16) float  g_outr[2][(size_t)NTOK * HDIM];     // rank-split

// ---------------------------------------------------------------------------
// Helpers
// ---------------------------------------------------------------------------
__device__ __forceinline__ uint32_t smem_u32(const void* p) {
    uint32_t a;
    asm("{ .reg .u64 t; cvta.to.shared.u64 t, %1; cvt.u32.u64 %0, t; }"
        : "=r"(a) : "l"(p));
    return a;
}
// 128B-row XOR swizzle
__device__ __forceinline__ uint32_t swz(uint32_t row, uint32_t byteoff) {
    uint32_t c16 = byteoff >> 4, lo = byteoff & 15;
    return row * 128 + (((c16 ^ (row & 7)) & 7) << 4) + lo;
}
__device__ __forceinline__ void cp16(uint32_t saddr, const void* gaddr) {
    asm volatile("cp.async.cg.shared.global [%0], [%1], 16;" :: "r"(saddr), "l"(gaddr));
}
#define CP_COMMIT() asm volatile("cp.async.commit_group;" ::: "memory")
#define CP_WAIT0()  asm volatile("cp.async.wait_group 0;" ::: "memory")
#define CP_WAIT1()  asm volatile("cp.async.wait_group 1;" ::: "memory")

__device__ __forceinline__ void ldsm_x4(uint32_t* r, uint32_t addr) {
    asm volatile("ldmatrix.sync.aligned.m8n8.x4.shared.b16 {%0,%1,%2,%3}, [%4];"
        : "=r"(r[0]), "=r"(r[1]), "=r"(r[2]), "=r"(r[3]) : "r"(addr));
}
__device__ __forceinline__ void mma_f16(float* d, const uint32_t* a, const uint32_t* b) {
    asm volatile(
        "mma.sync.aligned.m16n8k16.row.col.f32.f16.f16.f32 "
        "{%0,%1,%2,%3}, {%4,%5,%6,%7}, {%8,%9}, {%0,%1,%2,%3};"
        : "+f"(d[0]), "+f"(d[1]), "+f"(d[2]), "+f"(d[3])
        : "r"(a[0]), "r"(a[1]), "r"(a[2]), "r"(a[3]), "r"(b[0]), "r"(b[1]));
}

// ---------------------------------------------------------------------------
__global__ void reset_kernel() {
    if (threadIdx.x < NEXP) g_cnt[threadIdx.x] = 0;
}

// Fused: x fp32 -> fp16 plane AND router (top-2 + renorm + per-expert lists).
__global__ void prep_x(const float* __restrict__ x, const float* __restrict__ gw) {
    int tok = blockIdx.x * 8 + (threadIdx.x >> 5);
    int lane = threadIdx.x & 31;
    const float4* src = (const float4*)(x + (size_t)tok * DDIM);
    const float4* g4 = (const float4*)gw;
    uint2* xf = (uint2*)(g_xf + (size_t)tok * DDIM);

    float a0 = 0.f, a1 = 0.f, a2 = 0.f, a3 = 0.f;
#pragma unroll
    for (int j = 0; j < 16; j++) {
        int k4 = lane + j * 32;
        float4 v = src[k4];
        float4 w0 = g4[k4], w1 = g4[512 + k4], w2 = g4[1024 + k4], w3 = g4[1536 + k4];
        a0 = fmaf(v.x, w0.x, fmaf(v.y, w0.y, fmaf(v.z, w0.z, fmaf(v.w, w0.w, a0))));
        a1 = fmaf(v.x, w1.x, fmaf(v.y, w1.y, fmaf(v.z, w1.z, fmaf(v.w, w1.w, a1))));
        a2 = fmaf(v.x, w2.x, fmaf(v.y, w2.y, fmaf(v.z, w2.z, fmaf(v.w, w2.w, a2))));
        a3 = fmaf(v.x, w3.x, fmaf(v.y, w3.y, fmaf(v.z, w3.z, fmaf(v.w, w3.w, a3))));
        __half2 p0 = __floats2half2_rn(v.x, v.y);
        __half2 p1 = __floats2half2_rn(v.z, v.w);
        xf[k4] = make_uint2(*(uint32_t*)&p0, *(uint32_t*)&p1);
    }
#pragma unroll
    for (int o = 16; o; o >>= 1) {
        a0 += __shfl_xor_sync(0xffffffffu, a0, o);
        a1 += __shfl_xor_sync(0xffffffffu, a1, o);
        a2 += __shfl_xor_sync(0xffffffffu, a2, o);
        a3 += __shfl_xor_sync(0xffffffffu, a3, o);
    }
    if (lane == 0) {
        float l[4] = {a0, a1, a2, a3};
        int i0 = 0;
#pragma unroll
        for (int e = 1; e < 4; e++) if (l[e] > l[i0]) i0 = e;
        int i1 = (i0 == 0) ? 1 : 0;
#pragma unroll
        for (int e = 0; e < 4; e++) if (e != i0 && l[e] > l[i1]) i1 = e;
        float w0 = 1.0f / (1.0f + expf(l[i1] - l[i0]));
        float w1 = 1.0f - w0;
        int s0 = atomicAdd(&g_cnt[i0], 1);
        g_tok[i0][s0] = tok; g_wgt[i0][s0] = w0; g_rank[i0][s0] = 0;
        int s1 = atomicAdd(&g_cnt[i1], 1);
        g_tok[i1][s1] = tok; g_wgt[i1][s1] = w1; g_rank[i1][s1] = 1;
    }
}

// w [E][K][N] fp32 -> wt [E][N][K] fp16; z covers both weights (0-3: w1, 4-7: w2)
__global__ void transpose_w(const float* __restrict__ w1, const float* __restrict__ w2) {
    __shared__ float tile[32][33];
    int which = blockIdx.z >> 2;
    int e = blockIdx.z & 3;
    int n0 = blockIdx.x * 32, k0 = blockIdx.y * 32;
    const float* src = (which ? w2 : w1) + (size_t)e * DDIM * HDIM;
    int tx = threadIdx.x, ty = threadIdx.y;
#pragma unroll
    for (int i = 0; i < 4; i++) {
        int k = k0 + ty + i * 8;
        tile[ty + i * 8][tx] = src[(size_t)k * HDIM + n0 + tx];
    }
    __syncthreads();
    __half* of = which ? g_w2f : g_w1f;
#pragma unroll
    for (int i = 0; i < 4; i++) {
        int n = n0 + ty + i * 8;
        float v = tile[tx][ty + i * 8];
        size_t o = ((size_t)e * HDIM + n) * DDIM + k0 + tx;
        of[o] = __float2half_rn(v);
    }
}

// ---------------------------------------------------------------------------
// GEMM core: fp16, m16n8k16, ldmatrix, 32x64 warp tile (2 mt x 8 nt)
// 16 warps: wm = wid & 3 (4 x 32 rows), wn = wid >> 2 (4 x 64 cols)
// ---------------------------------------------------------------------------
__device__ __forceinline__ void compute_chunk(uint32_t base, int wm, int wn,
                                              int lane, float acc[2][8][4]) {
    uint32_t aF = base;
    uint32_t bF = base + TILE_A;

    uint32_t a_row  = (uint32_t)(wm * 32) + (lane & 15);
    uint32_t a_kb   = (uint32_t)((lane >> 4) << 4);
    uint32_t b_row0 = (uint32_t)(wn * 64) + (((lane >> 4) & 1) << 3) + (lane & 7);
    uint32_t b_kb   = (uint32_t)(((lane >> 3) & 1) << 4);

#pragma unroll
    for (int s = 0; s < 4; s++) {
        uint32_t boff = s * 32;
        uint32_t af[2][4];
#pragma unroll
        for (int mt = 0; mt < 2; mt++)
            ldsm_x4(af[mt], aF + swz(a_row + mt * 16, boff + a_kb));
#pragma unroll
        for (int p = 0; p < 4; p++) {          // p covers n-tiles 2p, 2p+1
            uint32_t rb[4];
            ldsm_x4(rb, bF + swz(b_row0 + p * 16, boff + b_kb));
#pragma unroll
            for (int mt = 0; mt < 2; mt++) {
                mma_f16(acc[mt][2 * p],     af[mt], rb);
                mma_f16(acc[mt][2 * p + 1], af[mt], rb + 2);
            }
        }
    }
}

// ---------------------------------------------------------------------------
// GEMM1: h1[e][m][:] = gelu(x[tok] @ w1[e] + b1[e]) -> fp16
// ---------------------------------------------------------------------------
__global__ void __launch_bounds__(NTHREADS, 1)
moe_gemm1(const float* __restrict__ b1) {
    int e = blockIdx.z;
    int cnt = g_cnt[e];
    int m0 = blockIdx.y * BM;
    if (m0 >= cnt) return;
    int n0 = blockIdx.x * BN;

    __shared__ int s_tok[BM];
    extern __shared__ char dynsm[];
    uint32_t ab = (smem_u32(dynsm) + 1023) & ~1023u;

    int tid = threadIdx.x;
    int wid = tid >> 5, lane = tid & 31;
    int wm = wid & 3, wn = wid >> 2;

    if (tid < BM) {
        int s = m0 + tid; if (s > cnt - 1) s = cnt - 1;
        s_tok[tid] = g_tok[e][s];
    }
    __syncthreads();

    const __half* wf = g_w1f + (size_t)e * HDIM * DDIM;

    float acc[2][8][4];
#pragma unroll
    for (int i = 0; i < 2; i++)
#pragma unroll
        for (int j = 0; j < 8; j++)
#pragma unroll
            for (int k = 0; k < 4; k++) acc[i][j][k] = 0.f;

    int r = tid >> 3, c16 = tid & 7;           // 512 threads: 64 rows x 8 chunks
    auto load_chunk = [&](int c, uint32_t bufb) {
        int k0 = c * BK;
#pragma unroll
        for (int i = 0; i < 2; i++) {           // A: 128 rows
            int rr = r + i * 64;
            uint32_t so = swz((uint32_t)rr, (uint32_t)(c16 * 16));
            cp16(ab + bufb + so, g_xf + (size_t)s_tok[rr] * DDIM + k0 + c16 * 8);
        }
#pragma unroll
        for (int i = 0; i < 4; i++) {           // B: 256 rows
            int rr = r + i * 64;
            uint32_t so = swz((uint32_t)rr, (uint32_t)(c16 * 16));
            cp16(ab + bufb + TILE_A + so, wf + (size_t)(n0 + rr) * DDIM + k0 + c16 * 8);
        }
        CP_COMMIT();
    };

    load_chunk(0, 0);
    load_chunk(1, STAGE_BYTES);
    for (int c = 0; c < NCH; c++) {
        if (c + 1 < NCH) CP_WAIT1(); else CP_WAIT0();
        __syncthreads();
        if (c + 2 < NCH) load_chunk(c + 2, (uint32_t)((c + 2) % NSTG) * STAGE_BYTES);
        compute_chunk(ab + (uint32_t)(c % NSTG) * STAGE_BYTES, wm, wn, lane, acc);
    }

    // Epilogue: bias + exact GELU -> fp16
    int g = lane >> 2, tig = lane & 3;
    __half* h1f = g_h1f + (size_t)e * NTOK * HDIM;
    const float* bias = b1 + (size_t)e * HDIM;
#pragma unroll
    for (int nt = 0; nt < 8; nt++) {
        int n = n0 + wn * 64 + nt * 8 + tig * 2;
        float bv0 = bias[n], bv1 = bias[n + 1];
#pragma unroll
        for (int mt = 0; mt < 2; mt++) {
#pragma unroll
            for (int half = 0; half < 2; half++) {
                int m = m0 + wm * 32 + mt * 16 + g + half * 8;
                if (m < cnt) {
                    float v0 = acc[mt][nt][half * 2 + 0] + bv0;
                    float v1 = acc[mt][nt][half * 2 + 1] + bv1;
                    float g0 = 0.5f * v0 * (1.0f + erff(v0 * 0.70710678118654752f));
                    float g1 = 0.5f * v1 * (1.0f + erff(v1 * 0.70710678118654752f));
                    __half2 hv = __floats2half2_rn(g0, g1);
                    *(uint32_t*)(h1f + (size_t)m * HDIM + n) = *(uint32_t*)&hv;
                }
            }
        }
    }
}

// ---------------------------------------------------------------------------
// GEMM2: g_outr[rank][tok][:] = wgt * (h1[e] @ w2[e] + b2[e])
// ---------------------------------------------------------------------------
__global__ void __launch_bounds__(NTHREADS, 1)
moe_gemm2(const float* __restrict__ b2) {
    int e = blockIdx.z;
    int cnt = g_cnt[e];
    int m0 = blockIdx.y * BM;
    if (m0 >= cnt) return;
    int n0 = blockIdx.x * BN;

    __shared__ int   s_tok[BM];
    __shared__ float s_wgt[BM];
    __shared__ int   s_rnk[BM];
    extern __shared__ char dynsm[];
    uint32_t ab = (smem_u32(dynsm) + 1023) & ~1023u;

    int tid = threadIdx.x;
    int wid = tid >> 5, lane = tid & 31;
    int wm = wid & 3, wn = wid >> 2;

    if (tid < BM) {
        int s = m0 + tid; if (s > cnt - 1) s = cnt - 1;
        s_tok[tid] = g_tok[e][s];
        s_wgt[tid] = g_wgt[e][s];
        s_rnk[tid] = g_rank[e][s];
    }
    __syncthreads();

    const __half* ahp = g_h1f + (size_t)e * NTOK * HDIM;
    const __half* wf = g_w2f + (size_t)e * HDIM * HDIM;

    float acc[2][8][4];
#pragma unroll
    for (int i = 0; i < 2; i++)
#pragma unroll
        for (int j = 0; j < 8; j++)
#pragma unroll
            for (int k = 0; k < 4; k++) acc[i][j][k] = 0.f;

    int r = tid >> 3, c16 = tid & 7;
    auto load_chunk = [&](int c, uint32_t bufb) {
        int k0 = c * BK;
#pragma unroll
        for (int i = 0; i < 2; i++) {
            int rr = r + i * 64;
            uint32_t so = swz((uint32_t)rr, (uint32_t)(c16 * 16));
            int mm = m0 + rr; if (mm > cnt - 1) mm = cnt - 1;
            cp16(ab + bufb + so, ahp + (size_t)mm * HDIM + k0 + c16 * 8);
        }
#pragma unroll
        for (int i = 0; i < 4; i++) {
            int rr = r + i * 64;
            uint32_t so = swz((uint32_t)rr, (uint32_t)(c16 * 16));
            cp16(ab + bufb + TILE_A + so, wf + (size_t)(n0 + rr) * HDIM + k0 + c16 * 8);
        }
        CP_COMMIT();
    };

    load_chunk(0, 0);
    load_chunk(1, STAGE_BYTES);
    for (int c = 0; c < NCH; c++) {
        if (c + 1 < NCH) CP_WAIT1(); else CP_WAIT0();
        __syncthreads();
        if (c + 2 < NCH) load_chunk(c + 2, (uint32_t)((c + 2) % NSTG) * STAGE_BYTES);
        compute_chunk(ab + (uint32_t)(c % NSTG) * STAGE_BYTES, wm, wn, lane, acc);
    }

    // Epilogue: (acc + b2) * wgt -> plain store into rank plane
    int g = lane >> 2, tig = lane & 3;
    const float* bias = b2 + (size_t)e * HDIM;
#pragma unroll
    for (int nt = 0; nt < 8; nt++) {
        int n = n0 + wn * 64 + nt * 8 + tig * 2;
        float bv0 = bias[n], bv1 = bias[n + 1];
#pragma unroll
        for (int mt = 0; mt < 2; mt++) {
#pragma unroll
            for (int half = 0; half < 2; half++) {
                int rl = wm * 32 + mt * 16 + g + half * 8;
                int m = m0 + rl;
                if (m < cnt) {
                    float w = s_wgt[rl];
                    float* dst = g_outr[s_rnk[rl]] + (size_t)s_tok[rl] * HDIM + n;
                    dst[0] = w * (acc[mt][nt][half * 2 + 0] + bv0);
                    dst[1] = w * (acc[mt][nt][half * 2 + 1] + bv1);
                }
            }
        }
    }
}

// ---------------------------------------------------------------------------
__global__ void combine_kernel(float4* __restrict__ out, long n4) {
    long i = (long)blockIdx.x * blockDim.x + threadIdx.x;
    long st = (long)gridDim.x * blockDim.x;
    const float4* r0 = (const float4*)g_outr[0];
    const float4* r1 = (const float4*)g_outr[1];
    for (; i < n4; i += st) {
        float4 a = r0[i], b = r1[i];
        out[i] = make_float4(a.x + b.x, a.y + b.y, a.z + b.z, a.w + b.w);
    }
}

// ---------------------------------------------------------------------------
extern "C" void kernel_launch(void* const* d_in, const int* in_sizes, int n_in,
                              void* d_out, int out_size) {
    const float* x  = (const float*)d_in[0];
    const float* gw = (const float*)d_in[1];
    const float* w1 = (const float*)d_in[2];
    const float* b1 = (const float*)d_in[3];
    const float* w2 = (const float*)d_in[4];
    const float* b2 = (const float*)d_in[5];
    float* out = (float*)d_out;

    cudaFuncSetAttribute(moe_gemm1, cudaFuncAttributeMaxDynamicSharedMemorySize, SMEM_TOTAL);
    cudaFuncSetAttribute(moe_gemm2, cudaFuncAttributeMaxDynamicSharedMemorySize, SMEM_TOTAL);

    reset_kernel<<<1, 32>>>();
    prep_x<<<NTOK / 8, 256>>>(x, gw);
    transpose_w<<<dim3(64, 64, 8), dim3(32, 8)>>>(w1, w2);

    moe_gemm1<<<dim3(HDIM / BN, NTOK / BM, NEXP), NTHREADS, SMEM_TOTAL>>>(b1);
    moe_gemm2<<<dim3(HDIM / BN, NTOK / BM, NEXP), NTHREADS, SMEM_TOTAL>>>(b2);
    combine_kernel<<<2048, 256>>>((float4*)out, (long)out_size / 4);
}